// round 7
// baseline (speedup 1.0000x reference)
#include <cuda_runtime.h>
#include <cuda_bf16.h>
#include <math.h>

#define DIM   3072
#define Hn    24
#define DH    128
#define INNER 3072
#define LI    4096
#define LT    512
#define Lseq  (LI + LT)        // 4608
#define MLPD  12288
#define EPSV  1e-6f

// CTA tile 128(M) x 256(N), KCH=32. smem: 2 stages x [Ahi|Alo|Bhi|Blo]
// A parts 128x32, B parts 256x32 bf16, rows padded to 40 halves.
#define KCH   32
#define SH    40
#define A_PART_BYTES (128 * SH * 2)        // 10240
#define B_PART_BYTES (256 * SH * 2)        // 20480
#define STAGE_BYTES (2 * A_PART_BYTES + 2 * B_PART_BYTES)   // 61440
#define SMEMSZ (2 * STAGE_BYTES)                            // 122880

typedef __nv_bfloat16 bf16;

// ---------------------------------------------------------------------------
// Scratch (device globals; allocation-free per harness rules)
// ---------------------------------------------------------------------------
__device__ float g_E[2 * 18432];
__device__ bf16  g_NHhi[(size_t)LI * DIM],  g_NHlo[(size_t)LI * DIM];
__device__ bf16  g_NEhi[(size_t)LT * DIM],  g_NElo[(size_t)LT * DIM];
__device__ float g_QKVI[(size_t)LI * 3 * INNER];
__device__ float g_QKVT[(size_t)LT * 3 * INNER];
__device__ bf16  g_Qhi[(size_t)Lseq * INNER], g_Qlo[(size_t)Lseq * INNER];
__device__ bf16  g_Khi[(size_t)Lseq * INNER], g_Klo[(size_t)Lseq * INNER];
__device__ bf16  g_Vnh[(size_t)Lseq * INNER],  g_Vnl[(size_t)Lseq * INNER];   // natural
__device__ bf16  g_VThi[(size_t)INNER * Lseq], g_VTlo[(size_t)INNER * Lseq];  // transposed
__device__ float g_S[(size_t)Lseq * Lseq];
__device__ bf16  g_Phi[(size_t)Lseq * Lseq], g_Plo[(size_t)Lseq * Lseq];
__device__ bf16  g_Ohi[(size_t)Lseq * INNER], g_Olo[(size_t)Lseq * INNER];
__device__ bf16  g_FFIhi[(size_t)LI * MLPD], g_FFIlo[(size_t)LI * MLPD];
__device__ bf16  g_FFThi[(size_t)LT * MLPD], g_FFTlo[(size_t)LT * MLPD];
// transposed (N,K) weights, bf16 hi/lo split
__device__ bf16 g_Wiqkv_h[(size_t)9216 * DIM],  g_Wiqkv_l[(size_t)9216 * DIM];
__device__ bf16 g_Weqkv_h[(size_t)9216 * DIM],  g_Weqkv_l[(size_t)9216 * DIM];
__device__ bf16 g_Wiprj_h[(size_t)DIM * INNER], g_Wiprj_l[(size_t)DIM * INNER];
__device__ bf16 g_Weprj_h[(size_t)DIM * INNER], g_Weprj_l[(size_t)DIM * INNER];
__device__ bf16 g_Wim1_h[(size_t)MLPD * DIM],   g_Wim1_l[(size_t)MLPD * DIM];
__device__ bf16 g_Wtm1_h[(size_t)MLPD * DIM],   g_Wtm1_l[(size_t)MLPD * DIM];
__device__ bf16 g_Wim2_h[(size_t)DIM * MLPD],   g_Wim2_l[(size_t)DIM * MLPD];
__device__ bf16 g_Wtm2_h[(size_t)DIM * MLPD],   g_Wtm2_l[(size_t)DIM * MLPD];

// ---------------------------------------------------------------------------
// Helpers
// ---------------------------------------------------------------------------
__device__ __forceinline__ void split_bf(float x, bf16& h, bf16& l) {
    h = __float2bfloat16(x);
    l = __float2bfloat16(x - __bfloat162float(h));
}

__device__ __forceinline__ unsigned s2u(const void* p) {
    unsigned a;
    asm("{ .reg .u64 t; cvta.to.shared.u64 t, %1; cvt.u32.u64 %0, t; }" : "=r"(a) : "l"(p));
    return a;
}

__device__ __forceinline__ void mma_bf16(float* c, const unsigned* a, const unsigned* b) {
    asm volatile(
        "mma.sync.aligned.m16n8k16.row.col.f32.bf16.bf16.f32 "
        "{%0,%1,%2,%3}, {%4,%5,%6,%7}, {%8,%9}, {%0,%1,%2,%3};"
        : "+f"(c[0]), "+f"(c[1]), "+f"(c[2]), "+f"(c[3])
        : "r"(a[0]), "r"(a[1]), "r"(a[2]), "r"(a[3]), "r"(b[0]), "r"(b[1]));
}

__device__ __forceinline__ void ldsm4(unsigned& r0, unsigned& r1, unsigned& r2, unsigned& r3,
                                      unsigned addr) {
    asm volatile("ldmatrix.sync.aligned.m8n8.x4.shared.b16 {%0,%1,%2,%3}, [%4];"
                 : "=r"(r0), "=r"(r1), "=r"(r2), "=r"(r3) : "r"(addr));
}

// ---------------------------------------------------------------------------
// bf16x3 split GEMM: C = epi(A @ B^T), A=[M,K] hi/lo bf16, B=[N,K] hi/lo bf16.
// acc += Ah*Bh + Ah*Bl + Al*Bh   (fp32 accumulate; lo*lo dropped)
// 128x256 CTA tile, KCH=32, 8 warps (2x4), warp tile 64x64, double-buffered,
// ldmatrix.x4 fragment loads, 1 CTA/SM.
// EPI: 0 -> Cf = scale*acc
//      1 -> split(acc) -> Chi/Clo
//      2 -> Cf = resid + gate[c]*(acc + bias[c])
//      3 -> split(gelu(acc + bias[c])) -> Chi/Clo
// Requires M%128==0, N%256==0, K%32==0.
// ---------------------------------------------------------------------------
template<int EPI>
__global__ void __launch_bounds__(256, 1)
gemm_bf3(const bf16* __restrict__ Ahi, const bf16* __restrict__ Alo,
         const bf16* __restrict__ Bhi, const bf16* __restrict__ Blo,
         float* __restrict__ Cf, bf16* __restrict__ Chi, bf16* __restrict__ Clo,
         int M, int N, int K, float scale,
         const float* __restrict__ bias, const float* __restrict__ gate,
         const float* __restrict__ resid)
{
    extern __shared__ char smem[];
    const int tid  = threadIdx.x;
    const int wid  = tid >> 5, lane = tid & 31;
    const int g    = lane >> 2, t = lane & 3;
    const int wm   = wid & 1;          // 2 warp rows x 64
    const int wn   = wid >> 1;         // 4 warp cols x 64
    const int row0 = blockIdx.y * 128;
    const int col0 = blockIdx.x * 256;
    const int T    = K >> 5;

    const unsigned sbase = s2u(smem);
    const bf16* gpA[2] = { Ahi + (size_t)row0 * K, Alo + (size_t)row0 * K };
    const bf16* gpB[2] = { Bhi + (size_t)col0 * K, Blo + (size_t)col0 * K };

    // ldmatrix per-lane offsets (bytes within a part)
    const int lr = lane & 7;
    const unsigned aoff = ((unsigned)(wm * 64 + ((lane >> 3) & 1) * 8 + lr) * SH
                           + (unsigned)(lane >> 4) * 8) * 2u;
    const unsigned boff = ((unsigned)(wn * 64 + (lane >> 4) * 8 + lr) * SH
                           + (unsigned)((lane >> 3) & 1) * 8) * 2u;

    auto load_stage = [&](int s, int kc) {
        unsigned st = sbase + (unsigned)s * STAGE_BYTES;
        #pragma unroll
        for (int p = 0; p < 2; p++) {     // A hi/lo: 512 chunks each
            #pragma unroll
            for (int i = 0; i < 2; i++) {
                int rem = (i << 8) + tid;
                int r = rem >> 2;
                int c = (rem & 3) << 3;
                unsigned sa = st + (unsigned)p * A_PART_BYTES
                                 + (unsigned)(r * (SH * 2) + c * 2);
                asm volatile("cp.async.cg.shared.global [%0], [%1], 16;"
                             :: "r"(sa), "l"(gpA[p] + (size_t)r * K + kc + c) : "memory");
            }
        }
        #pragma unroll
        for (int p = 0; p < 2; p++) {     // B hi/lo: 1024 chunks each
            #pragma unroll
            for (int i = 0; i < 4; i++) {
                int rem = (i << 8) + tid;
                int r = rem >> 2;
                int c = (rem & 3) << 3;
                unsigned sa = st + 2u * A_PART_BYTES + (unsigned)p * B_PART_BYTES
                                 + (unsigned)(r * (SH * 2) + c * 2);
                asm volatile("cp.async.cg.shared.global [%0], [%1], 16;"
                             :: "r"(sa), "l"(gpB[p] + (size_t)r * K + kc + c) : "memory");
            }
        }
    };

    float acc[4][8][4];
    #pragma unroll
    for (int i = 0; i < 4; i++)
        #pragma unroll
        for (int j = 0; j < 8; j++)
            #pragma unroll
            for (int q = 0; q < 4; q++) acc[i][j][q] = 0.f;

    load_stage(0, 0);
    asm volatile("cp.async.commit_group;" ::: "memory");

    for (int kt = 0; kt < T; kt++) {
        if (kt + 1 < T) {
            load_stage((kt + 1) & 1, (kt + 1) * KCH);
            asm volatile("cp.async.commit_group;" ::: "memory");
            asm volatile("cp.async.wait_group 1;" ::: "memory");
        } else {
            asm volatile("cp.async.wait_group 0;" ::: "memory");
        }
        __syncthreads();

        const unsigned stb = sbase + (unsigned)(kt & 1) * STAGE_BYTES;
        const unsigned Ahb = stb;
        const unsigned Alb = stb + A_PART_BYTES;
        const unsigned Bhb = stb + 2 * A_PART_BYTES;
        const unsigned Blb = Bhb + B_PART_BYTES;

        #pragma unroll
        for (int ks = 0; ks < 2; ks++) {
            const unsigned kb = (unsigned)ks * 32u;   // 16 halves = 32 bytes
            unsigned bh[8][2], bl[8][2], af[4][4];
            #pragma unroll
            for (int p = 0; p < 4; p++) {
                unsigned off = boff + (unsigned)p * (16 * SH * 2) + kb;
                ldsm4(bh[2*p][0], bh[2*p][1], bh[2*p+1][0], bh[2*p+1][1], Bhb + off);
                ldsm4(bl[2*p][0], bl[2*p][1], bl[2*p+1][0], bl[2*p+1][1], Blb + off);
            }
            #pragma unroll
            for (int mt = 0; mt < 4; mt++)
                ldsm4(af[mt][0], af[mt][1], af[mt][2], af[mt][3],
                      Ahb + aoff + (unsigned)mt * (16 * SH * 2) + kb);
            #pragma unroll
            for (int mt = 0; mt < 4; mt++)
                #pragma unroll
                for (int nt = 0; nt < 8; nt++)
                    mma_bf16(acc[mt][nt], af[mt], bh[nt]);
            #pragma unroll
            for (int mt = 0; mt < 4; mt++)
                #pragma unroll
                for (int nt = 0; nt < 8; nt++)
                    mma_bf16(acc[mt][nt], af[mt], bl[nt]);
            #pragma unroll
            for (int mt = 0; mt < 4; mt++)
                ldsm4(af[mt][0], af[mt][1], af[mt][2], af[mt][3],
                      Alb + aoff + (unsigned)mt * (16 * SH * 2) + kb);
            #pragma unroll
            for (int mt = 0; mt < 4; mt++)
                #pragma unroll
                for (int nt = 0; nt < 8; nt++)
                    mma_bf16(acc[mt][nt], af[mt], bh[nt]);
        }
        __syncthreads();
    }

    // epilogue
    #pragma unroll
    for (int mt = 0; mt < 4; mt++) {
        #pragma unroll
        for (int half = 0; half < 2; half++) {
            int row = row0 + wm * 64 + mt * 16 + g + half * 8;
            #pragma unroll
            for (int nt = 0; nt < 8; nt++) {
                int col = col0 + wn * 64 + nt * 8 + t * 2;
                size_t off = (size_t)row * N + col;
                float v0 = acc[mt][nt][half * 2];
                float v1 = acc[mt][nt][half * 2 + 1];
                if (EPI == 0) {
                    Cf[off]     = v0 * scale;
                    Cf[off + 1] = v1 * scale;
                } else if (EPI == 2) {
                    Cf[off]     = resid[off]     + gate[col]     * (v0 + bias[col]);
                    Cf[off + 1] = resid[off + 1] + gate[col + 1] * (v1 + bias[col + 1]);
                } else {
                    if (EPI == 3) {
                        float u0 = v0 + bias[col], u1 = v1 + bias[col + 1];
                        v0 = 0.5f * u0 * (1.f + tanhf(0.7978845608028654f *
                                 (u0 + 0.044715f * u0 * u0 * u0)));
                        v1 = 0.5f * u1 * (1.f + tanhf(0.7978845608028654f *
                                 (u1 + 0.044715f * u1 * u1 * u1)));
                    }
                    bf16 h0, l0, h1, l1;
                    split_bf(v0, h0, l0);
                    split_bf(v1, h1, l1);
                    *(__nv_bfloat162*)(Chi + off) = __nv_bfloat162(h0, h1);
                    *(__nv_bfloat162*)(Clo + off) = __nv_bfloat162(l0, l1);
                }
            }
        }
    }
}

// ---------------------------------------------------------------------------
// Weight transpose [K,N] -> [N,K], bf16 hi/lo split
// ---------------------------------------------------------------------------
__global__ void transpose_kernel(const float* __restrict__ src,
                                 bf16* __restrict__ dh, bf16* __restrict__ dl,
                                 int K, int N)
{
    __shared__ float t[32][33];
    int nb = blockIdx.x << 5, kb = blockIdx.y << 5;
    int tx = threadIdx.x, ty = threadIdx.y;
    #pragma unroll
    for (int i = 0; i < 4; i++)
        t[ty + i * 8][tx] = src[(size_t)(kb + ty + i * 8) * N + nb + tx];
    __syncthreads();
    #pragma unroll
    for (int i = 0; i < 4; i++) {
        bf16 h, l;
        split_bf(t[tx][ty + i * 8], h, l);
        size_t o = (size_t)(nb + ty + i * 8) * K + kb + tx;
        dh[o] = h; dl[o] = l;
    }
}

// ---------------------------------------------------------------------------
// bf16 pair transpose: [R,C] -> [C,R]  (for V -> V^T)
// ---------------------------------------------------------------------------
__global__ void transpose_bf_kernel(const bf16* __restrict__ sh_, const bf16* __restrict__ sl_,
                                    bf16* __restrict__ dh, bf16* __restrict__ dl,
                                    int R, int C)
{
    __shared__ bf16 th[32][34], tl[32][34];
    int cb = blockIdx.x << 5, rb = blockIdx.y << 5;
    int tx = threadIdx.x, ty = threadIdx.y;
    #pragma unroll
    for (int i = 0; i < 4; i++) {
        size_t o = (size_t)(rb + ty + i * 8) * C + cb + tx;
        th[ty + i * 8][tx] = sh_[o];
        tl[ty + i * 8][tx] = sl_[o];
    }
    __syncthreads();
    #pragma unroll
    for (int i = 0; i < 4; i++) {
        size_t o = (size_t)(cb + ty + i * 8) * R + rb + tx;
        dh[o] = th[tx][ty + i * 8];
        dl[o] = tl[tx][ty + i * 8];
    }
}

// ---------------------------------------------------------------------------
// adaLN embedding GEMV
// ---------------------------------------------------------------------------
__global__ void ada_gemv_kernel(const float* __restrict__ temb,
                                const float* __restrict__ Wi, const float* __restrict__ bi,
                                const float* __restrict__ Wt, const float* __restrict__ bt,
                                float* __restrict__ E)
{
    __shared__ float s[DIM];
    for (int i = threadIdx.x; i < DIM; i += 256) {
        float x = temb[i];
        s[i] = x / (1.f + expf(-x));
    }
    __syncthreads();
    int gcol = blockIdx.x * 256 + threadIdx.x;
    int which = gcol / 18432;
    int col = gcol - which * 18432;
    const float* W = which ? Wt : Wi;
    const float* b = which ? bt : bi;
    float acc = 0.f;
    for (int k = 0; k < DIM; k++)
        acc = fmaf(s[k], W[(size_t)k * 18432 + col], acc);
    E[gcol] = acc + b[col];
}

// ---------------------------------------------------------------------------
// LayerNorm + modulate -> bf16 hi/lo (feeds GEMM A operand)
// ---------------------------------------------------------------------------
__global__ void adaln_kernel(const float* xi, const float* xt,
                             const float* __restrict__ E, int off_shift, int off_scale,
                             bf16* oih, bf16* oil, bf16* oth, bf16* otl)
{
    __shared__ float shs[8], shq[8];
    int row = blockIdx.x;
    const float* x; bf16 *oh, *ol; const float* e;
    if (row < LI) {
        x = xi + (size_t)row * DIM;
        oh = oih + (size_t)row * DIM; ol = oil + (size_t)row * DIM; e = E;
    } else {
        int r = row - LI;
        x = xt + (size_t)r * DIM;
        oh = oth + (size_t)r * DIM; ol = otl + (size_t)r * DIM; e = E + 18432;
    }

    float sum = 0.f, sq = 0.f;
    for (int c = threadIdx.x; c < DIM; c += 256) {
        float v = x[c];
        sum += v; sq = fmaf(v, v, sq);
    }
    #pragma unroll
    for (int off = 16; off; off >>= 1) {
        sum += __shfl_xor_sync(0xffffffffu, sum, off);
        sq  += __shfl_xor_sync(0xffffffffu, sq,  off);
    }
    int w = threadIdx.x >> 5;
    if ((threadIdx.x & 31) == 0) { shs[w] = sum; shq[w] = sq; }
    __syncthreads();
    sum = 0.f; sq = 0.f;
    #pragma unroll
    for (int i = 0; i < 8; i++) { sum += shs[i]; sq += shq[i]; }
    float mean = sum * (1.f / DIM);
    float var  = sq * (1.f / DIM) - mean * mean;
    float rstd = rsqrtf(var + EPSV);
    for (int c = threadIdx.x; c < DIM; c += 256) {
        float v = (x[c] - mean) * rstd * (1.f + e[off_scale + c]) + e[off_shift + c];
        bf16 h, l; split_bf(v, h, l);
        oh[c] = h; ol[c] = l;
    }
}

// ---------------------------------------------------------------------------
// RMS-norm + RoPE + scatter: Q/K hi/lo row-major, V hi/lo NATURAL row-major
// ---------------------------------------------------------------------------
__global__ void rms_rope_kernel(const float* __restrict__ qkvt, const float* __restrict__ qkvi,
                                const float* __restrict__ rot,
                                const float* __restrict__ qs_i, const float* __restrict__ ks_i,
                                const float* __restrict__ qs_t, const float* __restrict__ ks_t,
                                bf16* Qh, bf16* Ql, bf16* Kh, bf16* Kl,
                                bf16* Vh, bf16* Vl)
{
    int token = blockIdx.x / Hn;
    int h     = blockIdx.x - token * Hn;
    int d     = threadIdx.x;

    const float* basep; const float* qs; const float* ks;
    if (token < LT) { basep = qkvt + (size_t)token * (3 * INNER);        qs = qs_t; ks = ks_t; }
    else            { basep = qkvi + (size_t)(token - LT) * (3 * INNER); qs = qs_i; ks = ks_i; }

    float qv = basep[            h * DH + d];
    float kv = basep[    INNER + h * DH + d];
    float vv = basep[2 * INNER + h * DH + d];

    float sq = qv * qv, sk = kv * kv;
    #pragma unroll
    for (int off = 16; off; off >>= 1) {
        sq += __shfl_xor_sync(0xffffffffu, sq, off);
        sk += __shfl_xor_sync(0xffffffffu, sk, off);
    }
    __shared__ float wq[4], wk[4];
    __shared__ float shq[DH], shk[DH];
    int w = d >> 5;
    if ((d & 31) == 0) { wq[w] = sq; wk[w] = sk; }
    __syncthreads();
    sq = wq[0] + wq[1] + wq[2] + wq[3];
    sk = wk[0] + wk[1] + wk[2] + wk[3];
    float qn = qv * rsqrtf(sq * (1.f / DH) + EPSV) * qs[d];
    float kn = kv * rsqrtf(sk * (1.f / DH) + EPSV) * ks[d];
    shq[d] = qn; shk[d] = kn;
    __syncthreads();

    int hh = d >> 1, j = d & 1;
    const float* f = &rot[(size_t)token * 256 + hh * 4 + j * 2];
    float f0 = f[0], f1 = f[1];
    float qo = f0 * shq[2 * hh] + f1 * shq[2 * hh + 1];
    float ko = f0 * shk[2 * hh] + f1 * shk[2 * hh + 1];

    size_t oidx = (size_t)token * INNER + h * DH + d;
    bf16 hq2, lq2, hk2, lk2, hv2, lv2;
    split_bf(qo, hq2, lq2);
    split_bf(ko, hk2, lk2);
    split_bf(vv, hv2, lv2);
    Qh[oidx] = hq2; Ql[oidx] = lq2;
    Kh[oidx] = hk2; Kl[oidx] = lk2;
    Vh[oidx] = hv2; Vl[oidx] = lv2;
}

// ---------------------------------------------------------------------------
// Row softmax over Lseq=4608 -> bf16 hi/lo probs (feeds O GEMM)
// ---------------------------------------------------------------------------
__global__ void softmax_kernel(const float* __restrict__ S, bf16* Ph, bf16* Pl)
{
    __shared__ float sh[8];
    const float* p = S + (size_t)blockIdx.x * Lseq;
    bf16* ph = Ph + (size_t)blockIdx.x * Lseq;
    bf16* pl = Pl + (size_t)blockIdx.x * Lseq;
    int tid = threadIdx.x;
    float v[18];
    float mx = -1e30f;
    #pragma unroll
    for (int i = 0; i < 18; i++) { v[i] = p[i * 256 + tid]; mx = fmaxf(mx, v[i]); }
    #pragma unroll
    for (int off = 16; off; off >>= 1) mx = fmaxf(mx, __shfl_xor_sync(0xffffffffu, mx, off));
    int w = tid >> 5;
    if ((tid & 31) == 0) sh[w] = mx;
    __syncthreads();
    mx = sh[0];
    #pragma unroll
    for (int i = 1; i < 8; i++) mx = fmaxf(mx, sh[i]);
    __syncthreads();
    float sum = 0.f;
    #pragma unroll
    for (int i = 0; i < 18; i++) { v[i] = expf(v[i] - mx); sum += v[i]; }
    #pragma unroll
    for (int off = 16; off; off >>= 1) sum += __shfl_xor_sync(0xffffffffu, sum, off);
    if ((tid & 31) == 0) sh[w] = sum;
    __syncthreads();
    sum = 0.f;
    #pragma unroll
    for (int i = 0; i < 8; i++) sum += sh[i];
    float inv = 1.f / sum;
    #pragma unroll
    for (int i = 0; i < 18; i++) {
        bf16 h, l; split_bf(v[i] * inv, h, l);
        ph[i * 256 + tid] = h; pl[i * 256 + tid] = l;
    }
}

// ---------------------------------------------------------------------------
// Launch
// ---------------------------------------------------------------------------
extern "C" void kernel_launch(void* const* d_in, const int* in_sizes, int n_in,
                              void* d_out, int out_size)
{
    const float* hidden  = (const float*)d_in[0];
    const float* enc     = (const float*)d_in[1];
    const float* temb    = (const float*)d_in[2];
    const float* rot     = (const float*)d_in[3];
    const float* W_iada  = (const float*)d_in[4];
    const float* b_iada  = (const float*)d_in[5];
    const float* W_tada  = (const float*)d_in[6];
    const float* b_tada  = (const float*)d_in[7];
    const float* W_iqkv  = (const float*)d_in[8];
    const float* W_eqkv  = (const float*)d_in[9];
    const float* W_iproj = (const float*)d_in[10];
    const float* b_iproj = (const float*)d_in[11];
    const float* W_eproj = (const float*)d_in[12];
    const float* b_eproj = (const float*)d_in[13];
    const float* q_scale  = (const float*)d_in[14];
    const float* k_scale  = (const float*)d_in[15];
    const float* eq_scale = (const float*)d_in[16];
    const float* ek_scale = (const float*)d_in[17];
    const float* W_imlp1 = (const float*)d_in[18];
    const float* b_imlp1 = (const float*)d_in[19];
    const float* W_imlp2 = (const float*)d_in[20];
    const float* b_imlp2 = (const float*)d_in[21];
    const float* W_tmlp1 = (const float*)d_in[22];
    const float* b_tmlp1 = (const float*)d_in[23];
    const float* W_tmlp2 = (const float*)d_in[24];
    const float* b_tmlp2 = (const float*)d_in[25];

    float* out = (float*)d_out;
    float* hs = out;
    float* es = out + (size_t)LI * DIM;

    float *E, *QKVI, *QKVT, *Sb;
    bf16 *NHh, *NHl, *NEh, *NEl, *Qh, *Ql, *Kh, *Kl, *Vnh, *Vnl, *VTh, *VTl;
    bf16 *Ph, *Pl, *Oh, *Ol, *FFIh, *FFIl, *FFTh, *FFTl;
    bf16 *Wiqkvh, *Wiqkvl, *Weqkvh, *Weqkvl, *Wiprjh, *Wiprjl, *Weprjh, *Weprjl;
    bf16 *Wim1h, *Wim1l, *Wtm1h, *Wtm1l, *Wim2h, *Wim2l, *Wtm2h, *Wtm2l;

    cudaGetSymbolAddress((void**)&E,     g_E);
    cudaGetSymbolAddress((void**)&QKVI,  g_QKVI);
    cudaGetSymbolAddress((void**)&QKVT,  g_QKVT);
    cudaGetSymbolAddress((void**)&Sb,    g_S);
    cudaGetSymbolAddress((void**)&NHh,   g_NHhi);  cudaGetSymbolAddress((void**)&NHl, g_NHlo);
    cudaGetSymbolAddress((void**)&NEh,   g_NEhi);  cudaGetSymbolAddress((void**)&NEl, g_NElo);
    cudaGetSymbolAddress((void**)&Qh,    g_Qhi);   cudaGetSymbolAddress((void**)&Ql,  g_Qlo);
    cudaGetSymbolAddress((void**)&Kh,    g_Khi);   cudaGetSymbolAddress((void**)&Kl,  g_Klo);
    cudaGetSymbolAddress((void**)&Vnh,   g_Vnh);   cudaGetSymbolAddress((void**)&Vnl, g_Vnl);
    cudaGetSymbolAddress((void**)&VTh,   g_VThi);  cudaGetSymbolAddress((void**)&VTl, g_VTlo);
    cudaGetSymbolAddress((void**)&Ph,    g_Phi);   cudaGetSymbolAddress((void**)&Pl,  g_Plo);
    cudaGetSymbolAddress((void**)&Oh,    g_Ohi);   cudaGetSymbolAddress((void**)&Ol,  g_Olo);
    cudaGetSymbolAddress((void**)&FFIh,  g_FFIhi); cudaGetSymbolAddress((void**)&FFIl, g_FFIlo);
    cudaGetSymbolAddress((void**)&FFTh,  g_FFThi); cudaGetSymbolAddress((void**)&FFTl, g_FFTlo);
    cudaGetSymbolAddress((void**)&Wiqkvh, g_Wiqkv_h); cudaGetSymbolAddress((void**)&Wiqkvl, g_Wiqkv_l);
    cudaGetSymbolAddress((void**)&Weqkvh, g_Weqkv_h); cudaGetSymbolAddress((void**)&Weqkvl, g_Weqkv_l);
    cudaGetSymbolAddress((void**)&Wiprjh, g_Wiprj_h); cudaGetSymbolAddress((void**)&Wiprjl, g_Wiprj_l);
    cudaGetSymbolAddress((void**)&Weprjh, g_Weprj_h); cudaGetSymbolAddress((void**)&Weprjl, g_Weprj_l);
    cudaGetSymbolAddress((void**)&Wim1h,  g_Wim1_h);  cudaGetSymbolAddress((void**)&Wim1l,  g_Wim1_l);
    cudaGetSymbolAddress((void**)&Wtm1h,  g_Wtm1_h);  cudaGetSymbolAddress((void**)&Wtm1l,  g_Wtm1_l);
    cudaGetSymbolAddress((void**)&Wim2h,  g_Wim2_h);  cudaGetSymbolAddress((void**)&Wim2l,  g_Wim2_l);
    cudaGetSymbolAddress((void**)&Wtm2h,  g_Wtm2_h);  cudaGetSymbolAddress((void**)&Wtm2l,  g_Wtm2_l);

    const float* Ei = E;
    const float* Et = E + 18432;

    cudaFuncSetAttribute(gemm_bf3<0>, cudaFuncAttributeMaxDynamicSharedMemorySize, SMEMSZ);
    cudaFuncSetAttribute(gemm_bf3<1>, cudaFuncAttributeMaxDynamicSharedMemorySize, SMEMSZ);
    cudaFuncSetAttribute(gemm_bf3<2>, cudaFuncAttributeMaxDynamicSharedMemorySize, SMEMSZ);
    cudaFuncSetAttribute(gemm_bf3<3>, cudaFuncAttributeMaxDynamicSharedMemorySize, SMEMSZ);

    dim3 tb(32, 8);
    transpose_kernel<<<dim3(9216 / 32, DIM / 32), tb>>>(W_iqkv,  Wiqkvh, Wiqkvl, DIM,  9216);
    transpose_kernel<<<dim3(9216 / 32, DIM / 32), tb>>>(W_eqkv,  Weqkvh, Weqkvl, DIM,  9216);
    transpose_kernel<<<dim3(DIM / 32, INNER / 32), tb>>>(W_iproj, Wiprjh, Wiprjl, INNER, DIM);
    transpose_kernel<<<dim3(DIM / 32, INNER / 32), tb>>>(W_eproj, Weprjh, Weprjl, INNER, DIM);
    transpose_kernel<<<dim3(MLPD / 32, DIM / 32), tb>>>(W_imlp1, Wim1h, Wim1l, DIM,  MLPD);
    transpose_kernel<<<dim3(MLPD / 32, DIM / 32), tb>>>(W_tmlp1, Wtm1h, Wtm1l, DIM,  MLPD);
    transpose_kernel<<<dim3(DIM / 32, MLPD / 32), tb>>>(W_imlp2, Wim2h, Wim2l, MLPD, DIM);
    transpose_kernel<<<dim3(DIM / 32, MLPD / 32), tb>>>(W_tmlp2, Wtm2h, Wtm2l, MLPD, DIM);

    // 1. adaLN embeddings
    ada_gemv_kernel<<<144, 256>>>(temb, W_iada, b_iada, W_tada, b_tada, E);

    // 2. LN + modulate (msa): shift=sm(0), scale=cm(3072)
    adaln_kernel<<<LI + LT, 256>>>(hidden, enc, E, 0, 3072, NHh, NHl, NEh, NEl);

    // 3-4. QKV projections -> fp32
    gemm_bf3<0><<<dim3(9216 / 256, LI / 128), 256, SMEMSZ>>>(
        NHh, NHl, Wiqkvh, Wiqkvl, QKVI, nullptr, nullptr,
        LI, 9216, DIM, 1.f, nullptr, nullptr, nullptr);
    gemm_bf3<0><<<dim3(9216 / 256, LT / 128), 256, SMEMSZ>>>(
        NEh, NEl, Weqkvh, Weqkvl, QKVT, nullptr, nullptr,
        LT, 9216, DIM, 1.f, nullptr, nullptr, nullptr);

    // 5. RMS + RoPE + concat scatter (V natural) -> then coalesced V transpose
    rms_rope_kernel<<<Lseq * Hn, 128>>>(QKVT, QKVI, rot, q_scale, k_scale, eq_scale, ek_scale,
                                        Qh, Ql, Kh, Kl, Vnh, Vnl);
    transpose_bf_kernel<<<dim3(INNER / 32, Lseq / 32), tb>>>(Vnh, Vnl, VTh, VTl, Lseq, INNER);

    // 6. S = (Q K^T) / sqrt(DH) -> fp32
    gemm_bf3<0><<<dim3(Lseq / 256, Lseq / 128), 256, SMEMSZ>>>(
        Qh, Ql, Kh, Kl, Sb, nullptr, nullptr,
        Lseq, Lseq, INNER, 0.08838834764831843f, nullptr, nullptr, nullptr);

    // 7. softmax -> P hi/lo
    softmax_kernel<<<Lseq, 256>>>(Sb, Ph, Pl);

    // 8. O = P V -> hi/lo   (B = V^T [INNER, Lseq])
    gemm_bf3<1><<<dim3(INNER / 256, Lseq / 128), 256, SMEMSZ>>>(
        Ph, Pl, VTh, VTl, nullptr, Oh, Ol,
        Lseq, INNER, Lseq, 1.f, nullptr, nullptr, nullptr);

    // 9-10. output projections with fused gated residual -> fp32 d_out
    gemm_bf3<2><<<dim3(DIM / 256, LI / 128), 256, SMEMSZ>>>(
        Oh + (size_t)LT * INNER, Ol + (size_t)LT * INNER, Wiprjh, Wiprjl, hs, nullptr, nullptr,
        LI, DIM, INNER, 1.f, b_iproj, Ei + 6144, hidden);
    gemm_bf3<2><<<dim3(DIM / 256, LT / 128), 256, SMEMSZ>>>(
        Oh, Ol, Weprjh, Weprjl, es, nullptr, nullptr,
        LT, DIM, INNER, 1.f, b_eproj, Et + 6144, enc);

    // 11. LN + modulate (mlp): shift=sp(9216), scale=cp(12288)
    adaln_kernel<<<LI + LT, 256>>>(hs, es, E, 9216, 12288, NHh, NHl, NEh, NEl);

    // 12-13. MLP1 + fused gelu -> hi/lo
    gemm_bf3<3><<<dim3(MLPD / 256, LI / 128), 256, SMEMSZ>>>(
        NHh, NHl, Wim1h, Wim1l, nullptr, FFIh, FFIl,
        LI, MLPD, DIM, 1.f, b_imlp1, nullptr, nullptr);
    gemm_bf3<3><<<dim3(MLPD / 256, LT / 128), 256, SMEMSZ>>>(
        NEh, NEl, Wtm1h, Wtm1l, nullptr, FFTh, FFTl,
        LT, MLPD, DIM, 1.f, b_tmlp1, nullptr, nullptr);

    // 14-15. MLP2 with fused gated residual (in-place on d_out)
    gemm_bf3<2><<<dim3(DIM / 256, LI / 128), 256, SMEMSZ>>>(
        FFIh, FFIl, Wim2h, Wim2l, hs, nullptr, nullptr,
        LI, DIM, MLPD, 1.f, b_imlp2, Ei + 15360, hs);
    gemm_bf3<2><<<dim3(DIM / 256, LT / 128), 256, SMEMSZ>>>(
        FFTh, FFTl, Wtm2h, Wtm2l, es, nullptr, nullptr,
        LT, DIM, MLPD, 1.f, b_tmlp2, Et + 15360, es);
}

// round 8
// speedup vs baseline: 1.0040x; 1.0040x over previous
#include <cuda_runtime.h>
#include <cuda_bf16.h>
#include <math.h>

#define DIM   3072
#define Hn    24
#define DH    128
#define INNER 3072
#define LI    4096
#define LT    512
#define Lseq  (LI + LT)        // 4608
#define MLPD  12288
#define EPSV  1e-6f

// CTA tile 128(M) x 256(N), 512 threads (16 warps, 2x8), KCH=32, 3 stages.
#define KCH   32
#define SH    40
#define A_PART_BYTES (128 * SH * 2)        // 10240
#define B_PART_BYTES (256 * SH * 2)        // 20480
#define STAGE_BYTES (2 * A_PART_BYTES + 2 * B_PART_BYTES)   // 61440
#define SMEMSZ (3 * STAGE_BYTES)                            // 184320

typedef __nv_bfloat16 bf16;

// ---------------------------------------------------------------------------
// Scratch (device globals; allocation-free per harness rules)
// ---------------------------------------------------------------------------
__device__ float g_E[2 * 18432];
__device__ bf16  g_NHhi[(size_t)LI * DIM],  g_NHlo[(size_t)LI * DIM];
__device__ bf16  g_NEhi[(size_t)LT * DIM],  g_NElo[(size_t)LT * DIM];
__device__ float g_QKVI[(size_t)LI * 3 * INNER];
__device__ float g_QKVT[(size_t)LT * 3 * INNER];
__device__ bf16  g_Qhi[(size_t)Lseq * INNER], g_Qlo[(size_t)Lseq * INNER];
__device__ bf16  g_Khi[(size_t)Lseq * INNER], g_Klo[(size_t)Lseq * INNER];
__device__ bf16  g_Vnh[(size_t)Lseq * INNER],  g_Vnl[(size_t)Lseq * INNER];   // natural
__device__ bf16  g_VThi[(size_t)INNER * Lseq], g_VTlo[(size_t)INNER * Lseq];  // transposed
__device__ float g_S[(size_t)Lseq * Lseq];
__device__ bf16  g_Phi[(size_t)Lseq * Lseq], g_Plo[(size_t)Lseq * Lseq];
__device__ bf16  g_Ohi[(size_t)Lseq * INNER], g_Olo[(size_t)Lseq * INNER];
__device__ bf16  g_FFIhi[(size_t)LI * MLPD], g_FFIlo[(size_t)LI * MLPD];
__device__ bf16  g_FFThi[(size_t)LT * MLPD], g_FFTlo[(size_t)LT * MLPD];
// transposed (N,K) weights, bf16 hi/lo split
__device__ bf16 g_Wiqkv_h[(size_t)9216 * DIM],  g_Wiqkv_l[(size_t)9216 * DIM];
__device__ bf16 g_Weqkv_h[(size_t)9216 * DIM],  g_Weqkv_l[(size_t)9216 * DIM];
__device__ bf16 g_Wiprj_h[(size_t)DIM * INNER], g_Wiprj_l[(size_t)DIM * INNER];
__device__ bf16 g_Weprj_h[(size_t)DIM * INNER], g_Weprj_l[(size_t)DIM * INNER];
__device__ bf16 g_Wim1_h[(size_t)MLPD * DIM],   g_Wim1_l[(size_t)MLPD * DIM];
__device__ bf16 g_Wtm1_h[(size_t)MLPD * DIM],   g_Wtm1_l[(size_t)MLPD * DIM];
__device__ bf16 g_Wim2_h[(size_t)DIM * MLPD],   g_Wim2_l[(size_t)DIM * MLPD];
__device__ bf16 g_Wtm2_h[(size_t)DIM * MLPD],   g_Wtm2_l[(size_t)DIM * MLPD];

// ---------------------------------------------------------------------------
// Helpers
// ---------------------------------------------------------------------------
__device__ __forceinline__ void split_bf(float x, bf16& h, bf16& l) {
    h = __float2bfloat16(x);
    l = __float2bfloat16(x - __bfloat162float(h));
}

__device__ __forceinline__ unsigned s2u(const void* p) {
    unsigned a;
    asm("{ .reg .u64 t; cvta.to.shared.u64 t, %1; cvt.u32.u64 %0, t; }" : "=r"(a) : "l"(p));
    return a;
}

__device__ __forceinline__ void mma_bf16(float* c, const unsigned* a, const unsigned* b) {
    asm volatile(
        "mma.sync.aligned.m16n8k16.row.col.f32.bf16.bf16.f32 "
        "{%0,%1,%2,%3}, {%4,%5,%6,%7}, {%8,%9}, {%0,%1,%2,%3};"
        : "+f"(c[0]), "+f"(c[1]), "+f"(c[2]), "+f"(c[3])
        : "r"(a[0]), "r"(a[1]), "r"(a[2]), "r"(a[3]), "r"(b[0]), "r"(b[1]));
}

__device__ __forceinline__ void ldsm4(unsigned& r0, unsigned& r1, unsigned& r2, unsigned& r3,
                                      unsigned addr) {
    asm volatile("ldmatrix.sync.aligned.m8n8.x4.shared.b16 {%0,%1,%2,%3}, [%4];"
                 : "=r"(r0), "=r"(r1), "=r"(r2), "=r"(r3) : "r"(addr));
}

// ---------------------------------------------------------------------------
// bf16x3 split GEMM: C = epi(A @ B^T), A=[M,K] hi/lo bf16, B=[N,K] hi/lo bf16.
// acc += Ah*Bh + Ah*Bl + Al*Bh   (fp32 accumulate; lo*lo dropped)
// 128x256 CTA tile, 512 threads (16 warps 2x8), warp tile 64x32, KCH=32,
// 3-stage cp.async, ldmatrix.x4 fragment loads.
// EPI: 0 -> Cf = scale*acc
//      1 -> split(acc) -> Chi/Clo
//      2 -> Cf = resid + gate[c]*(acc + bias[c])
//      3 -> split(gelu(acc + bias[c])) -> Chi/Clo
// Requires M%128==0, N%256==0, K%32==0, K/32 >= 3.
// ---------------------------------------------------------------------------
template<int EPI>
__global__ void __launch_bounds__(512, 1)
gemm_bf3(const bf16* __restrict__ Ahi, const bf16* __restrict__ Alo,
         const bf16* __restrict__ Bhi, const bf16* __restrict__ Blo,
         float* __restrict__ Cf, bf16* __restrict__ Chi, bf16* __restrict__ Clo,
         int M, int N, int K, float scale,
         const float* __restrict__ bias, const float* __restrict__ gate,
         const float* __restrict__ resid)
{
    extern __shared__ char smem[];
    const int tid  = threadIdx.x;
    const int wid  = tid >> 5, lane = tid & 31;
    const int g    = lane >> 2, t = lane & 3;
    const int wm   = wid & 1;          // 2 warp rows x 64
    const int wn   = wid >> 1;         // 8 warp cols x 32
    const int row0 = blockIdx.y * 128;
    const int col0 = blockIdx.x * 256;
    const int T    = K >> 5;

    const unsigned sbase = s2u(smem);
    const bf16* gpA[2] = { Ahi + (size_t)row0 * K, Alo + (size_t)row0 * K };
    const bf16* gpB[2] = { Bhi + (size_t)col0 * K, Blo + (size_t)col0 * K };

    // ldmatrix per-lane offsets (bytes within a part)
    const int lr = lane & 7;
    const unsigned aoff = ((unsigned)(wm * 64 + ((lane >> 3) & 1) * 8 + lr) * SH
                           + (unsigned)(lane >> 4) * 8) * 2u;
    const unsigned boff = ((unsigned)(wn * 32 + (lane >> 4) * 8 + lr) * SH
                           + (unsigned)((lane >> 3) & 1) * 8) * 2u;

    auto load_stage = [&](int s, int kc) {
        unsigned st = sbase + (unsigned)s * STAGE_BYTES;
        // A hi/lo: 512 chunks each -> 1 per thread
        #pragma unroll
        for (int p = 0; p < 2; p++) {
            int r = tid >> 2;
            int c = (tid & 3) << 3;
            unsigned sa = st + (unsigned)p * A_PART_BYTES
                             + (unsigned)(r * (SH * 2) + c * 2);
            asm volatile("cp.async.cg.shared.global [%0], [%1], 16;"
                         :: "r"(sa), "l"(gpA[p] + (size_t)r * K + kc + c) : "memory");
        }
        // B hi/lo: 1024 chunks each -> 2 per thread
        #pragma unroll
        for (int p = 0; p < 2; p++) {
            #pragma unroll
            for (int i = 0; i < 2; i++) {
                int rem = (i << 9) + tid;
                int r = rem >> 2;
                int c = (rem & 3) << 3;
                unsigned sa = st + 2u * A_PART_BYTES + (unsigned)p * B_PART_BYTES
                                 + (unsigned)(r * (SH * 2) + c * 2);
                asm volatile("cp.async.cg.shared.global [%0], [%1], 16;"
                             :: "r"(sa), "l"(gpB[p] + (size_t)r * K + kc + c) : "memory");
            }
        }
    };

    float acc[4][4][4];
    #pragma unroll
    for (int i = 0; i < 4; i++)
        #pragma unroll
        for (int j = 0; j < 4; j++)
            #pragma unroll
            for (int q = 0; q < 4; q++) acc[i][j][q] = 0.f;

    load_stage(0, 0);
    asm volatile("cp.async.commit_group;" ::: "memory");
    load_stage(1, KCH);
    asm volatile("cp.async.commit_group;" ::: "memory");

    for (int kt = 0; kt < T; kt++) {
        if (kt + 2 < T)
            load_stage((kt + 2) % 3, (kt + 2) * KCH);
        asm volatile("cp.async.commit_group;" ::: "memory");
        asm volatile("cp.async.wait_group 2;" ::: "memory");
        __syncthreads();

        const unsigned stb = sbase + (unsigned)(kt % 3) * STAGE_BYTES;
        const unsigned Ahb = stb;
        const unsigned Alb = stb + A_PART_BYTES;
        const unsigned Bhb = stb + 2 * A_PART_BYTES;
        const unsigned Blb = Bhb + B_PART_BYTES;

        #pragma unroll
        for (int ks = 0; ks < 2; ks++) {
            const unsigned kb = (unsigned)ks * 32u;   // 16 halves = 32 bytes
            unsigned bh[4][2], bl[4][2], af[4][4];
            #pragma unroll
            for (int p = 0; p < 2; p++) {
                unsigned off = boff + (unsigned)p * (16 * SH * 2) + kb;
                ldsm4(bh[2*p][0], bh[2*p][1], bh[2*p+1][0], bh[2*p+1][1], Bhb + off);
                ldsm4(bl[2*p][0], bl[2*p][1], bl[2*p+1][0], bl[2*p+1][1], Blb + off);
            }
            #pragma unroll
            for (int mt = 0; mt < 4; mt++)
                ldsm4(af[mt][0], af[mt][1], af[mt][2], af[mt][3],
                      Ahb + aoff + (unsigned)mt * (16 * SH * 2) + kb);
            #pragma unroll
            for (int mt = 0; mt < 4; mt++)
                #pragma unroll
                for (int nt = 0; nt < 4; nt++)
                    mma_bf16(acc[mt][nt], af[mt], bh[nt]);
            #pragma unroll
            for (int mt = 0; mt < 4; mt++)
                #pragma unroll
                for (int nt = 0; nt < 4; nt++)
                    mma_bf16(acc[mt][nt], af[mt], bl[nt]);
            #pragma unroll
            for (int mt = 0; mt < 4; mt++)
                ldsm4(af[mt][0], af[mt][1], af[mt][2], af[mt][3],
                      Alb + aoff + (unsigned)mt * (16 * SH * 2) + kb);
            #pragma unroll
            for (int mt = 0; mt < 4; mt++)
                #pragma unroll
                for (int nt = 0; nt < 4; nt++)
                    mma_bf16(acc[mt][nt], af[mt], bh[nt]);
        }
        __syncthreads();
    }

    // epilogue
    #pragma unroll
    for (int mt = 0; mt < 4; mt++) {
        #pragma unroll
        for (int half = 0; half < 2; half++) {
            int row = row0 + wm * 64 + mt * 16 + g + half * 8;
            #pragma unroll
            for (int nt = 0; nt < 4; nt++) {
                int col = col0 + wn * 32 + nt * 8 + t * 2;
                size_t off = (size_t)row * N + col;
                float v0 = acc[mt][nt][half * 2];
                float v1 = acc[mt][nt][half * 2 + 1];
                if (EPI == 0) {
                    Cf[off]     = v0 * scale;
                    Cf[off + 1] = v1 * scale;
                } else if (EPI == 2) {
                    Cf[off]     = resid[off]     + gate[col]     * (v0 + bias[col]);
                    Cf[off + 1] = resid[off + 1] + gate[col + 1] * (v1 + bias[col + 1]);
                } else {
                    if (EPI == 3) {
                        float u0 = v0 + bias[col], u1 = v1 + bias[col + 1];
                        v0 = 0.5f * u0 * (1.f + tanhf(0.7978845608028654f *
                                 (u0 + 0.044715f * u0 * u0 * u0)));
                        v1 = 0.5f * u1 * (1.f + tanhf(0.7978845608028654f *
                                 (u1 + 0.044715f * u1 * u1 * u1)));
                    }
                    bf16 h0, l0, h1, l1;
                    split_bf(v0, h0, l0);
                    split_bf(v1, h1, l1);
                    *(__nv_bfloat162*)(Chi + off) = __nv_bfloat162(h0, h1);
                    *(__nv_bfloat162*)(Clo + off) = __nv_bfloat162(l0, l1);
                }
            }
        }
    }
}

// ---------------------------------------------------------------------------
// Weight transpose [K,N] -> [N,K], bf16 hi/lo split
// ---------------------------------------------------------------------------
__global__ void transpose_kernel(const float* __restrict__ src,
                                 bf16* __restrict__ dh, bf16* __restrict__ dl,
                                 int K, int N)
{
    __shared__ float t[32][33];
    int nb = blockIdx.x << 5, kb = blockIdx.y << 5;
    int tx = threadIdx.x, ty = threadIdx.y;
    #pragma unroll
    for (int i = 0; i < 4; i++)
        t[ty + i * 8][tx] = src[(size_t)(kb + ty + i * 8) * N + nb + tx];
    __syncthreads();
    #pragma unroll
    for (int i = 0; i < 4; i++) {
        bf16 h, l;
        split_bf(t[tx][ty + i * 8], h, l);
        size_t o = (size_t)(nb + ty + i * 8) * K + kb + tx;
        dh[o] = h; dl[o] = l;
    }
}

// ---------------------------------------------------------------------------
// bf16 pair transpose: [R,C] -> [C,R]  (for V -> V^T)
// ---------------------------------------------------------------------------
__global__ void transpose_bf_kernel(const bf16* __restrict__ sh_, const bf16* __restrict__ sl_,
                                    bf16* __restrict__ dh, bf16* __restrict__ dl,
                                    int R, int C)
{
    __shared__ bf16 th[32][34], tl[32][34];
    int cb = blockIdx.x << 5, rb = blockIdx.y << 5;
    int tx = threadIdx.x, ty = threadIdx.y;
    #pragma unroll
    for (int i = 0; i < 4; i++) {
        size_t o = (size_t)(rb + ty + i * 8) * C + cb + tx;
        th[ty + i * 8][tx] = sh_[o];
        tl[ty + i * 8][tx] = sl_[o];
    }
    __syncthreads();
    #pragma unroll
    for (int i = 0; i < 4; i++) {
        size_t o = (size_t)(cb + ty + i * 8) * R + rb + tx;
        dh[o] = th[tx][ty + i * 8];
        dl[o] = tl[tx][ty + i * 8];
    }
}

// ---------------------------------------------------------------------------
// adaLN embedding GEMV
// ---------------------------------------------------------------------------
__global__ void ada_gemv_kernel(const float* __restrict__ temb,
                                const float* __restrict__ Wi, const float* __restrict__ bi,
                                const float* __restrict__ Wt, const float* __restrict__ bt,
                                float* __restrict__ E)
{
    __shared__ float s[DIM];
    for (int i = threadIdx.x; i < DIM; i += 256) {
        float x = temb[i];
        s[i] = x / (1.f + expf(-x));
    }
    __syncthreads();
    int gcol = blockIdx.x * 256 + threadIdx.x;
    int which = gcol / 18432;
    int col = gcol - which * 18432;
    const float* W = which ? Wt : Wi;
    const float* b = which ? bt : bi;
    float acc = 0.f;
    for (int k = 0; k < DIM; k++)
        acc = fmaf(s[k], W[(size_t)k * 18432 + col], acc);
    E[gcol] = acc + b[col];
}

// ---------------------------------------------------------------------------
// LayerNorm + modulate -> bf16 hi/lo (feeds GEMM A operand)
// ---------------------------------------------------------------------------
__global__ void adaln_kernel(const float* xi, const float* xt,
                             const float* __restrict__ E, int off_shift, int off_scale,
                             bf16* oih, bf16* oil, bf16* oth, bf16* otl)
{
    __shared__ float shs[8], shq[8];
    int row = blockIdx.x;
    const float* x; bf16 *oh, *ol; const float* e;
    if (row < LI) {
        x = xi + (size_t)row * DIM;
        oh = oih + (size_t)row * DIM; ol = oil + (size_t)row * DIM; e = E;
    } else {
        int r = row - LI;
        x = xt + (size_t)r * DIM;
        oh = oth + (size_t)r * DIM; ol = otl + (size_t)r * DIM; e = E + 18432;
    }

    float sum = 0.f, sq = 0.f;
    for (int c = threadIdx.x; c < DIM; c += 256) {
        float v = x[c];
        sum += v; sq = fmaf(v, v, sq);
    }
    #pragma unroll
    for (int off = 16; off; off >>= 1) {
        sum += __shfl_xor_sync(0xffffffffu, sum, off);
        sq  += __shfl_xor_sync(0xffffffffu, sq,  off);
    }
    int w = threadIdx.x >> 5;
    if ((threadIdx.x & 31) == 0) { shs[w] = sum; shq[w] = sq; }
    __syncthreads();
    sum = 0.f; sq = 0.f;
    #pragma unroll
    for (int i = 0; i < 8; i++) { sum += shs[i]; sq += shq[i]; }
    float mean = sum * (1.f / DIM);
    float var  = sq * (1.f / DIM) - mean * mean;
    float rstd = rsqrtf(var + EPSV);
    for (int c = threadIdx.x; c < DIM; c += 256) {
        float v = (x[c] - mean) * rstd * (1.f + e[off_scale + c]) + e[off_shift + c];
        bf16 h, l; split_bf(v, h, l);
        oh[c] = h; ol[c] = l;
    }
}

// ---------------------------------------------------------------------------
// RMS-norm + RoPE + scatter: Q/K hi/lo row-major, V hi/lo NATURAL row-major
// ---------------------------------------------------------------------------
__global__ void rms_rope_kernel(const float* __restrict__ qkvt, const float* __restrict__ qkvi,
                                const float* __restrict__ rot,
                                const float* __restrict__ qs_i, const float* __restrict__ ks_i,
                                const float* __restrict__ qs_t, const float* __restrict__ ks_t,
                                bf16* Qh, bf16* Ql, bf16* Kh, bf16* Kl,
                                bf16* Vh, bf16* Vl)
{
    int token = blockIdx.x / Hn;
    int h     = blockIdx.x - token * Hn;
    int d     = threadIdx.x;

    const float* basep; const float* qs; const float* ks;
    if (token < LT) { basep = qkvt + (size_t)token * (3 * INNER);        qs = qs_t; ks = ks_t; }
    else            { basep = qkvi + (size_t)(token - LT) * (3 * INNER); qs = qs_i; ks = ks_i; }

    float qv = basep[            h * DH + d];
    float kv = basep[    INNER + h * DH + d];
    float vv = basep[2 * INNER + h * DH + d];

    float sq = qv * qv, sk = kv * kv;
    #pragma unroll
    for (int off = 16; off; off >>= 1) {
        sq += __shfl_xor_sync(0xffffffffu, sq, off);
        sk += __shfl_xor_sync(0xffffffffu, sk, off);
    }
    __shared__ float wq[4], wk[4];
    __shared__ float shq[DH], shk[DH];
    int w = d >> 5;
    if ((d & 31) == 0) { wq[w] = sq; wk[w] = sk; }
    __syncthreads();
    sq = wq[0] + wq[1] + wq[2] + wq[3];
    sk = wk[0] + wk[1] + wk[2] + wk[3];
    float qn = qv * rsqrtf(sq * (1.f / DH) + EPSV) * qs[d];
    float kn = kv * rsqrtf(sk * (1.f / DH) + EPSV) * ks[d];
    shq[d] = qn; shk[d] = kn;
    __syncthreads();

    int hh = d >> 1, j = d & 1;
    const float* f = &rot[(size_t)token * 256 + hh * 4 + j * 2];
    float f0 = f[0], f1 = f[1];
    float qo = f0 * shq[2 * hh] + f1 * shq[2 * hh + 1];
    float ko = f0 * shk[2 * hh] + f1 * shk[2 * hh + 1];

    size_t oidx = (size_t)token * INNER + h * DH + d;
    bf16 hq2, lq2, hk2, lk2, hv2, lv2;
    split_bf(qo, hq2, lq2);
    split_bf(ko, hk2, lk2);
    split_bf(vv, hv2, lv2);
    Qh[oidx] = hq2; Ql[oidx] = lq2;
    Kh[oidx] = hk2; Kl[oidx] = lk2;
    Vh[oidx] = hv2; Vl[oidx] = lv2;
}

// ---------------------------------------------------------------------------
// Row softmax over Lseq=4608 -> bf16 hi/lo probs (feeds O GEMM)
// ---------------------------------------------------------------------------
__global__ void softmax_kernel(const float* __restrict__ S, bf16* Ph, bf16* Pl)
{
    __shared__ float sh[8];
    const float* p = S + (size_t)blockIdx.x * Lseq;
    bf16* ph = Ph + (size_t)blockIdx.x * Lseq;
    bf16* pl = Pl + (size_t)blockIdx.x * Lseq;
    int tid = threadIdx.x;
    float v[18];
    float mx = -1e30f;
    #pragma unroll
    for (int i = 0; i < 18; i++) { v[i] = p[i * 256 + tid]; mx = fmaxf(mx, v[i]); }
    #pragma unroll
    for (int off = 16; off; off >>= 1) mx = fmaxf(mx, __shfl_xor_sync(0xffffffffu, mx, off));
    int w = tid >> 5;
    if ((tid & 31) == 0) sh[w] = mx;
    __syncthreads();
    mx = sh[0];
    #pragma unroll
    for (int i = 1; i < 8; i++) mx = fmaxf(mx, sh[i]);
    __syncthreads();
    float sum = 0.f;
    #pragma unroll
    for (int i = 0; i < 18; i++) { v[i] = expf(v[i] - mx); sum += v[i]; }
    #pragma unroll
    for (int off = 16; off; off >>= 1) sum += __shfl_xor_sync(0xffffffffu, sum, off);
    if ((tid & 31) == 0) sh[w] = sum;
    __syncthreads();
    sum = 0.f;
    #pragma unroll
    for (int i = 0; i < 8; i++) sum += sh[i];
    float inv = 1.f / sum;
    #pragma unroll
    for (int i = 0; i < 18; i++) {
        bf16 h, l; split_bf(v[i] * inv, h, l);
        ph[i * 256 + tid] = h; pl[i * 256 + tid] = l;
    }
}

// ---------------------------------------------------------------------------
// Launch
// ---------------------------------------------------------------------------
extern "C" void kernel_launch(void* const* d_in, const int* in_sizes, int n_in,
                              void* d_out, int out_size)
{
    const float* hidden  = (const float*)d_in[0];
    const float* enc     = (const float*)d_in[1];
    const float* temb    = (const float*)d_in[2];
    const float* rot     = (const float*)d_in[3];
    const float* W_iada  = (const float*)d_in[4];
    const float* b_iada  = (const float*)d_in[5];
    const float* W_tada  = (const float*)d_in[6];
    const float* b_tada  = (const float*)d_in[7];
    const float* W_iqkv  = (const float*)d_in[8];
    const float* W_eqkv  = (const float*)d_in[9];
    const float* W_iproj = (const float*)d_in[10];
    const float* b_iproj = (const float*)d_in[11];
    const float* W_eproj = (const float*)d_in[12];
    const float* b_eproj = (const float*)d_in[13];
    const float* q_scale  = (const float*)d_in[14];
    const float* k_scale  = (const float*)d_in[15];
    const float* eq_scale = (const float*)d_in[16];
    const float* ek_scale = (const float*)d_in[17];
    const float* W_imlp1 = (const float*)d_in[18];
    const float* b_imlp1 = (const float*)d_in[19];
    const float* W_imlp2 = (const float*)d_in[20];
    const float* b_imlp2 = (const float*)d_in[21];
    const float* W_tmlp1 = (const float*)d_in[22];
    const float* b_tmlp1 = (const float*)d_in[23];
    const float* W_tmlp2 = (const float*)d_in[24];
    const float* b_tmlp2 = (const float*)d_in[25];

    float* out = (float*)d_out;
    float* hs = out;
    float* es = out + (size_t)LI * DIM;

    float *E, *QKVI, *QKVT, *Sb;
    bf16 *NHh, *NHl, *NEh, *NEl, *Qh, *Ql, *Kh, *Kl, *Vnh, *Vnl, *VTh, *VTl;
    bf16 *Ph, *Pl, *Oh, *Ol, *FFIh, *FFIl, *FFTh, *FFTl;
    bf16 *Wiqkvh, *Wiqkvl, *Weqkvh, *Weqkvl, *Wiprjh, *Wiprjl, *Weprjh, *Weprjl;
    bf16 *Wim1h, *Wim1l, *Wtm1h, *Wtm1l, *Wim2h, *Wim2l, *Wtm2h, *Wtm2l;

    cudaGetSymbolAddress((void**)&E,     g_E);
    cudaGetSymbolAddress((void**)&QKVI,  g_QKVI);
    cudaGetSymbolAddress((void**)&QKVT,  g_QKVT);
    cudaGetSymbolAddress((void**)&Sb,    g_S);
    cudaGetSymbolAddress((void**)&NHh,   g_NHhi);  cudaGetSymbolAddress((void**)&NHl, g_NHlo);
    cudaGetSymbolAddress((void**)&NEh,   g_NEhi);  cudaGetSymbolAddress((void**)&NEl, g_NElo);
    cudaGetSymbolAddress((void**)&Qh,    g_Qhi);   cudaGetSymbolAddress((void**)&Ql,  g_Qlo);
    cudaGetSymbolAddress((void**)&Kh,    g_Khi);   cudaGetSymbolAddress((void**)&Kl,  g_Klo);
    cudaGetSymbolAddress((void**)&Vnh,   g_Vnh);   cudaGetSymbolAddress((void**)&Vnl, g_Vnl);
    cudaGetSymbolAddress((void**)&VTh,   g_VThi);  cudaGetSymbolAddress((void**)&VTl, g_VTlo);
    cudaGetSymbolAddress((void**)&Ph,    g_Phi);   cudaGetSymbolAddress((void**)&Pl,  g_Plo);
    cudaGetSymbolAddress((void**)&Oh,    g_Ohi);   cudaGetSymbolAddress((void**)&Ol,  g_Olo);
    cudaGetSymbolAddress((void**)&FFIh,  g_FFIhi); cudaGetSymbolAddress((void**)&FFIl, g_FFIlo);
    cudaGetSymbolAddress((void**)&FFTh,  g_FFThi); cudaGetSymbolAddress((void**)&FFTl, g_FFTlo);
    cudaGetSymbolAddress((void**)&Wiqkvh, g_Wiqkv_h); cudaGetSymbolAddress((void**)&Wiqkvl, g_Wiqkv_l);
    cudaGetSymbolAddress((void**)&Weqkvh, g_Weqkv_h); cudaGetSymbolAddress((void**)&Weqkvl, g_Weqkv_l);
    cudaGetSymbolAddress((void**)&Wiprjh, g_Wiprj_h); cudaGetSymbolAddress((void**)&Wiprjl, g_Wiprj_l);
    cudaGetSymbolAddress((void**)&Weprjh, g_Weprj_h); cudaGetSymbolAddress((void**)&Weprjl, g_Weprj_l);
    cudaGetSymbolAddress((void**)&Wim1h,  g_Wim1_h);  cudaGetSymbolAddress((void**)&Wim1l,  g_Wim1_l);
    cudaGetSymbolAddress((void**)&Wtm1h,  g_Wtm1_h);  cudaGetSymbolAddress((void**)&Wtm1l,  g_Wtm1_l);
    cudaGetSymbolAddress((void**)&Wim2h,  g_Wim2_h);  cudaGetSymbolAddress((void**)&Wim2l,  g_Wim2_l);
    cudaGetSymbolAddress((void**)&Wtm2h,  g_Wtm2_h);  cudaGetSymbolAddress((void**)&Wtm2l,  g_Wtm2_l);

    const float* Ei = E;
    const float* Et = E + 18432;

    cudaFuncSetAttribute(gemm_bf3<0>, cudaFuncAttributeMaxDynamicSharedMemorySize, SMEMSZ);
    cudaFuncSetAttribute(gemm_bf3<1>, cudaFuncAttributeMaxDynamicSharedMemorySize, SMEMSZ);
    cudaFuncSetAttribute(gemm_bf3<2>, cudaFuncAttributeMaxDynamicSharedMemorySize, SMEMSZ);
    cudaFuncSetAttribute(gemm_bf3<3>, cudaFuncAttributeMaxDynamicSharedMemorySize, SMEMSZ);

    dim3 tb(32, 8);
    transpose_kernel<<<dim3(9216 / 32, DIM / 32), tb>>>(W_iqkv,  Wiqkvh, Wiqkvl, DIM,  9216);
    transpose_kernel<<<dim3(9216 / 32, DIM / 32), tb>>>(W_eqkv,  Weqkvh, Weqkvl, DIM,  9216);
    transpose_kernel<<<dim3(DIM / 32, INNER / 32), tb>>>(W_iproj, Wiprjh, Wiprjl, INNER, DIM);
    transpose_kernel<<<dim3(DIM / 32, INNER / 32), tb>>>(W_eproj, Weprjh, Weprjl, INNER, DIM);
    transpose_kernel<<<dim3(MLPD / 32, DIM / 32), tb>>>(W_imlp1, Wim1h, Wim1l, DIM,  MLPD);
    transpose_kernel<<<dim3(MLPD / 32, DIM / 32), tb>>>(W_tmlp1, Wtm1h, Wtm1l, DIM,  MLPD);
    transpose_kernel<<<dim3(DIM / 32, MLPD / 32), tb>>>(W_imlp2, Wim2h, Wim2l, MLPD, DIM);
    transpose_kernel<<<dim3(DIM / 32, MLPD / 32), tb>>>(W_tmlp2, Wtm2h, Wtm2l, MLPD, DIM);

    // 1. adaLN embeddings
    ada_gemv_kernel<<<144, 256>>>(temb, W_iada, b_iada, W_tada, b_tada, E);

    // 2. LN + modulate (msa): shift=sm(0), scale=cm(3072)
    adaln_kernel<<<LI + LT, 256>>>(hidden, enc, E, 0, 3072, NHh, NHl, NEh, NEl);

    // 3-4. QKV projections -> fp32
    gemm_bf3<0><<<dim3(9216 / 256, LI / 128), 512, SMEMSZ>>>(
        NHh, NHl, Wiqkvh, Wiqkvl, QKVI, nullptr, nullptr,
        LI, 9216, DIM, 1.f, nullptr, nullptr, nullptr);
    gemm_bf3<0><<<dim3(9216 / 256, LT / 128), 512, SMEMSZ>>>(
        NEh, NEl, Weqkvh, Weqkvl, QKVT, nullptr, nullptr,
        LT, 9216, DIM, 1.f, nullptr, nullptr, nullptr);

    // 5. RMS + RoPE + concat scatter (V natural) -> then coalesced V transpose
    rms_rope_kernel<<<Lseq * Hn, 128>>>(QKVT, QKVI, rot, q_scale, k_scale, eq_scale, ek_scale,
                                        Qh, Ql, Kh, Kl, Vnh, Vnl);
    transpose_bf_kernel<<<dim3(INNER / 32, Lseq / 32), tb>>>(Vnh, Vnl, VTh, VTl, Lseq, INNER);

    // 6. S = (Q K^T) / sqrt(DH) -> fp32
    gemm_bf3<0><<<dim3(Lseq / 256, Lseq / 128), 512, SMEMSZ>>>(
        Qh, Ql, Kh, Kl, Sb, nullptr, nullptr,
        Lseq, Lseq, INNER, 0.08838834764831843f, nullptr, nullptr, nullptr);

    // 7. softmax -> P hi/lo
    softmax_kernel<<<Lseq, 256>>>(Sb, Ph, Pl);

    // 8. O = P V -> hi/lo   (B = V^T [INNER, Lseq])
    gemm_bf3<1><<<dim3(INNER / 256, Lseq / 128), 512, SMEMSZ>>>(
        Ph, Pl, VTh, VTl, nullptr, Oh, Ol,
        Lseq, INNER, Lseq, 1.f, nullptr, nullptr, nullptr);

    // 9-10. output projections with fused gated residual -> fp32 d_out
    gemm_bf3<2><<<dim3(DIM / 256, LI / 128), 512, SMEMSZ>>>(
        Oh + (size_t)LT * INNER, Ol + (size_t)LT * INNER, Wiprjh, Wiprjl, hs, nullptr, nullptr,
        LI, DIM, INNER, 1.f, b_iproj, Ei + 6144, hidden);
    gemm_bf3<2><<<dim3(DIM / 256, LT / 128), 512, SMEMSZ>>>(
        Oh, Ol, Weprjh, Weprjl, es, nullptr, nullptr,
        LT, DIM, INNER, 1.f, b_eproj, Et + 6144, enc);

    // 11. LN + modulate (mlp): shift=sp(9216), scale=cp(12288)
    adaln_kernel<<<LI + LT, 256>>>(hs, es, E, 9216, 12288, NHh, NHl, NEh, NEl);

    // 12-13. MLP1 + fused gelu -> hi/lo
    gemm_bf3<3><<<dim3(MLPD / 256, LI / 128), 512, SMEMSZ>>>(
        NHh, NHl, Wim1h, Wim1l, nullptr, FFIh, FFIl,
        LI, MLPD, DIM, 1.f, b_imlp1, nullptr, nullptr);
    gemm_bf3<3><<<dim3(MLPD / 256, LT / 128), 512, SMEMSZ>>>(
        NEh, NEl, Wtm1h, Wtm1l, nullptr, FFTh, FFTl,
        LT, MLPD, DIM, 1.f, b_tmlp1, nullptr, nullptr);

    // 14-15. MLP2 with fused gated residual (in-place on d_out)
    gemm_bf3<2><<<dim3(DIM / 256, LI / 128), 512, SMEMSZ>>>(
        FFIh, FFIl, Wim2h, Wim2l, hs, nullptr, nullptr,
        LI, DIM, MLPD, 1.f, b_imlp2, Ei + 15360, hs);
    gemm_bf3<2><<<dim3(DIM / 256, LT / 128), 512, SMEMSZ>>>(
        FFTh, FFTl, Wtm2h, Wtm2l, es, nullptr, nullptr,
        LT, DIM, MLPD, 1.f, b_tmlp2, Et + 15360, es);
}

// round 9
// speedup vs baseline: 1.1890x; 1.1843x over previous
#include <cuda_runtime.h>
#include <cuda_bf16.h>
#include <math.h>

#define DIM   3072
#define Hn    24
#define DH    128
#define INNER 3072
#define LI    4096
#define LT    512
#define Lseq  (LI + LT)        // 4608
#define MLPD  12288
#define EPSV  1e-6f

// R6 config: CTA tile 128x128, 8 warps (2x4), KCH=32, 2 stages, 2 CTAs/SM.
#define KCH   32
#define SH    40                           // row stride in halves
#define PART_HALVES (128 * SH)             // 5120 halves = 10240 B
#define STAGE_BYTES (4 * PART_HALVES * 2)  // 40960
#define SMEMSZ (2 * STAGE_BYTES)           // 81920

typedef __nv_bfloat16 bf16;

// ---------------------------------------------------------------------------
// Scratch (device globals; allocation-free per harness rules)
// ---------------------------------------------------------------------------
__device__ float g_E[2 * 18432];
__device__ bf16  g_NHhi[(size_t)LI * DIM],  g_NHlo[(size_t)LI * DIM];
__device__ bf16  g_NEhi[(size_t)LT * DIM],  g_NElo[(size_t)LT * DIM];
__device__ float g_QKVI[(size_t)LI * 3 * INNER];
__device__ float g_QKVT[(size_t)LT * 3 * INNER];
__device__ bf16  g_Qhi[(size_t)Lseq * INNER], g_Qlo[(size_t)Lseq * INNER];
__device__ bf16  g_Khi[(size_t)Lseq * INNER], g_Klo[(size_t)Lseq * INNER];
__device__ bf16  g_Vnh[(size_t)Lseq * INNER],  g_Vnl[(size_t)Lseq * INNER];   // natural
__device__ bf16  g_VThi[(size_t)INNER * Lseq], g_VTlo[(size_t)INNER * Lseq];  // transposed
__device__ float g_S[(size_t)Lseq * Lseq];
__device__ bf16  g_Phi[(size_t)Lseq * Lseq], g_Plo[(size_t)Lseq * Lseq];
__device__ bf16  g_Ohi[(size_t)Lseq * INNER], g_Olo[(size_t)Lseq * INNER];
__device__ bf16  g_FFIhi[(size_t)LI * MLPD], g_FFIlo[(size_t)LI * MLPD];
__device__ bf16  g_FFThi[(size_t)LT * MLPD], g_FFTlo[(size_t)LT * MLPD];
// transposed (N,K) weights, bf16 hi/lo split
__device__ bf16 g_Wiqkv_h[(size_t)9216 * DIM],  g_Wiqkv_l[(size_t)9216 * DIM];
__device__ bf16 g_Weqkv_h[(size_t)9216 * DIM],  g_Weqkv_l[(size_t)9216 * DIM];
__device__ bf16 g_Wiprj_h[(size_t)DIM * INNER], g_Wiprj_l[(size_t)DIM * INNER];
__device__ bf16 g_Weprj_h[(size_t)DIM * INNER], g_Weprj_l[(size_t)DIM * INNER];
__device__ bf16 g_Wim1_h[(size_t)MLPD * DIM],   g_Wim1_l[(size_t)MLPD * DIM];
__device__ bf16 g_Wtm1_h[(size_t)MLPD * DIM],   g_Wtm1_l[(size_t)MLPD * DIM];
__device__ bf16 g_Wim2_h[(size_t)DIM * MLPD],   g_Wim2_l[(size_t)DIM * MLPD];
__device__ bf16 g_Wtm2_h[(size_t)DIM * MLPD],   g_Wtm2_l[(size_t)DIM * MLPD];

// ---------------------------------------------------------------------------
// Helpers
// ---------------------------------------------------------------------------
__device__ __forceinline__ void split_bf(float x, bf16& h, bf16& l) {
    h = __float2bfloat16(x);
    l = __float2bfloat16(x - __bfloat162float(h));
}

__device__ __forceinline__ unsigned s2u(const void* p) {
    unsigned a;
    asm("{ .reg .u64 t; cvta.to.shared.u64 t, %1; cvt.u32.u64 %0, t; }" : "=r"(a) : "l"(p));
    return a;
}

__device__ __forceinline__ void mma_bf16(float* c, const unsigned* a, const unsigned* b) {
    asm volatile(
        "mma.sync.aligned.m16n8k16.row.col.f32.bf16.bf16.f32 "
        "{%0,%1,%2,%3}, {%4,%5,%6,%7}, {%8,%9}, {%0,%1,%2,%3};"
        : "+f"(c[0]), "+f"(c[1]), "+f"(c[2]), "+f"(c[3])
        : "r"(a[0]), "r"(a[1]), "r"(a[2]), "r"(a[3]), "r"(b[0]), "r"(b[1]));
}

__device__ __forceinline__ void ldsm4(unsigned& r0, unsigned& r1, unsigned& r2, unsigned& r3,
                                      unsigned addr) {
    asm volatile("ldmatrix.sync.aligned.m8n8.x4.shared.b16 {%0,%1,%2,%3}, [%4];"
                 : "=r"(r0), "=r"(r1), "=r"(r2), "=r"(r3) : "r"(addr));
}

// Per-problem pointer pack: allows fusing the img and txt GEMMs of one stage
// into a single launch (img rows first, txt rows after M0).
struct GemmSet {
    const bf16 *Ah, *Al, *Bh, *Bl;
    float* Cf;
    bf16 *Chi, *Clo;
    const float *bias, *gate, *resid;
};

// ---------------------------------------------------------------------------
// bf16x3 split GEMM: C = epi(A @ B^T). Two problem sets share one launch:
// blockIdx.y*128 < M0 -> set0 (row0 local), else set1 (row0 - M0).
// acc += Ah*Bh + Ah*Bl + Al*Bh   (fp32 accumulate; lo*lo dropped)
// 128x128 CTA tile, KCH=32, 8 warps (2x4), warp tile 64x32, double-buffered,
// ldmatrix.x4 fragment loads, 2 CTAs/SM.
// EPI: 0 -> Cf = scale*acc ; 1 -> split(acc) ; 2 -> resid + gate*(acc+bias) ;
//      3 -> split(gelu(acc+bias))
// ---------------------------------------------------------------------------
template<int EPI>
__global__ void __launch_bounds__(256, 2)
gemm_bf3(GemmSet s0, GemmSet s1, int M0, int N, int K, float scale)
{
    extern __shared__ char smem[];
    const int tid  = threadIdx.x;
    const int wid  = tid >> 5, lane = tid & 31;
    const int g    = lane >> 2, t = lane & 3;
    const int wm   = wid & 1;
    const int wn   = wid >> 1;
    int row0 = blockIdx.y * 128;
    const GemmSet s = (row0 < M0) ? s0 : s1;
    if (row0 >= M0) row0 -= M0;
    const int col0 = blockIdx.x * 128;
    const int T    = K >> 5;

    const unsigned sbase = s2u(smem);
    const bf16* gp[4] = { s.Ah + (size_t)row0 * K, s.Al + (size_t)row0 * K,
                          s.Bh + (size_t)col0 * K, s.Bl + (size_t)col0 * K };

    // ldmatrix per-lane offsets (bytes within a part)
    const int lr = lane & 7;
    const unsigned aoff = ((unsigned)(wm * 64 + ((lane >> 3) & 1) * 8 + lr) * SH
                           + (unsigned)(lane >> 4) * 8) * 2u;
    const unsigned boff = ((unsigned)(wn * 32 + (lane >> 4) * 8 + lr) * SH
                           + (unsigned)((lane >> 3) & 1) * 8) * 2u;

    auto load_stage = [&](int st_, int kc) {
        unsigned st = sbase + (unsigned)st_ * STAGE_BYTES;
        #pragma unroll
        for (int p = 0; p < 8; p++) {
            const int part = p >> 1;
            int rem = ((p & 1) << 8) + tid;
            int r = rem >> 2;
            int c = (rem & 3) << 3;
            unsigned sa = st + (unsigned)part * (PART_HALVES * 2)
                             + (unsigned)(r * (SH * 2) + c * 2);
            asm volatile("cp.async.cg.shared.global [%0], [%1], 16;"
                         :: "r"(sa), "l"(gp[part] + (size_t)r * K + kc + c) : "memory");
        }
    };

    float acc[4][4][4];
    #pragma unroll
    for (int i = 0; i < 4; i++)
        #pragma unroll
        for (int j = 0; j < 4; j++)
            #pragma unroll
            for (int q = 0; q < 4; q++) acc[i][j][q] = 0.f;

    load_stage(0, 0);
    asm volatile("cp.async.commit_group;" ::: "memory");

    for (int kt = 0; kt < T; kt++) {
        if (kt + 1 < T) {
            load_stage((kt + 1) & 1, (kt + 1) * KCH);
            asm volatile("cp.async.commit_group;" ::: "memory");
            asm volatile("cp.async.wait_group 1;" ::: "memory");
        } else {
            asm volatile("cp.async.wait_group 0;" ::: "memory");
        }
        __syncthreads();

        const unsigned stb = sbase + (unsigned)(kt & 1) * STAGE_BYTES;
        const unsigned Ahb = stb;
        const unsigned Alb = stb + PART_HALVES * 2;
        const unsigned Bhb = stb + 2 * PART_HALVES * 2;
        const unsigned Blb = stb + 3 * PART_HALVES * 2;

        #pragma unroll
        for (int ks = 0; ks < 2; ks++) {
            const unsigned kb = (unsigned)ks * 32u;
            unsigned bh[4][2], bl[4][2], af[4][4];
            #pragma unroll
            for (int p = 0; p < 2; p++) {
                unsigned off = boff + (unsigned)p * (16 * SH * 2) + kb;
                ldsm4(bh[2*p][0], bh[2*p][1], bh[2*p+1][0], bh[2*p+1][1], Bhb + off);
                ldsm4(bl[2*p][0], bl[2*p][1], bl[2*p+1][0], bl[2*p+1][1], Blb + off);
            }
            #pragma unroll
            for (int mt = 0; mt < 4; mt++)
                ldsm4(af[mt][0], af[mt][1], af[mt][2], af[mt][3],
                      Ahb + aoff + (unsigned)mt * (16 * SH * 2) + kb);
            #pragma unroll
            for (int mt = 0; mt < 4; mt++)
                #pragma unroll
                for (int nt = 0; nt < 4; nt++)
                    mma_bf16(acc[mt][nt], af[mt], bh[nt]);
            #pragma unroll
            for (int mt = 0; mt < 4; mt++)
                #pragma unroll
                for (int nt = 0; nt < 4; nt++)
                    mma_bf16(acc[mt][nt], af[mt], bl[nt]);
            #pragma unroll
            for (int mt = 0; mt < 4; mt++)
                ldsm4(af[mt][0], af[mt][1], af[mt][2], af[mt][3],
                      Alb + aoff + (unsigned)mt * (16 * SH * 2) + kb);
            #pragma unroll
            for (int mt = 0; mt < 4; mt++)
                #pragma unroll
                for (int nt = 0; nt < 4; nt++)
                    mma_bf16(acc[mt][nt], af[mt], bh[nt]);
        }
        __syncthreads();
    }

    // epilogue
    #pragma unroll
    for (int mt = 0; mt < 4; mt++) {
        #pragma unroll
        for (int half = 0; half < 2; half++) {
            int row = row0 + wm * 64 + mt * 16 + g + half * 8;
            #pragma unroll
            for (int nt = 0; nt < 4; nt++) {
                int col = col0 + wn * 32 + nt * 8 + t * 2;
                size_t off = (size_t)row * N + col;
                float v0 = acc[mt][nt][half * 2];
                float v1 = acc[mt][nt][half * 2 + 1];
                if (EPI == 0) {
                    s.Cf[off]     = v0 * scale;
                    s.Cf[off + 1] = v1 * scale;
                } else if (EPI == 2) {
                    s.Cf[off]     = s.resid[off]     + s.gate[col]     * (v0 + s.bias[col]);
                    s.Cf[off + 1] = s.resid[off + 1] + s.gate[col + 1] * (v1 + s.bias[col + 1]);
                } else {
                    if (EPI == 3) {
                        float u0 = v0 + s.bias[col], u1 = v1 + s.bias[col + 1];
                        v0 = 0.5f * u0 * (1.f + tanhf(0.7978845608028654f *
                                 (u0 + 0.044715f * u0 * u0 * u0)));
                        v1 = 0.5f * u1 * (1.f + tanhf(0.7978845608028654f *
                                 (u1 + 0.044715f * u1 * u1 * u1)));
                    }
                    bf16 h0, l0, h1, l1;
                    split_bf(v0, h0, l0);
                    split_bf(v1, h1, l1);
                    *(__nv_bfloat162*)(s.Chi + off) = __nv_bfloat162(h0, h1);
                    *(__nv_bfloat162*)(s.Clo + off) = __nv_bfloat162(l0, l1);
                }
            }
        }
    }
}

// ---------------------------------------------------------------------------
// Weight transpose [K,N] -> [N,K], bf16 hi/lo split
// ---------------------------------------------------------------------------
__global__ void transpose_kernel(const float* __restrict__ src,
                                 bf16* __restrict__ dh, bf16* __restrict__ dl,
                                 int K, int N)
{
    __shared__ float t[32][33];
    int nb = blockIdx.x << 5, kb = blockIdx.y << 5;
    int tx = threadIdx.x, ty = threadIdx.y;
    #pragma unroll
    for (int i = 0; i < 4; i++)
        t[ty + i * 8][tx] = src[(size_t)(kb + ty + i * 8) * N + nb + tx];
    __syncthreads();
    #pragma unroll
    for (int i = 0; i < 4; i++) {
        bf16 h, l;
        split_bf(t[tx][ty + i * 8], h, l);
        size_t o = (size_t)(nb + ty + i * 8) * K + kb + tx;
        dh[o] = h; dl[o] = l;
    }
}

// ---------------------------------------------------------------------------
// bf16 pair transpose: [R,C] -> [C,R]  (for V -> V^T)
// ---------------------------------------------------------------------------
__global__ void transpose_bf_kernel(const bf16* __restrict__ sh_, const bf16* __restrict__ sl_,
                                    bf16* __restrict__ dh, bf16* __restrict__ dl,
                                    int R, int C)
{
    __shared__ bf16 th[32][34], tl[32][34];
    int cb = blockIdx.x << 5, rb = blockIdx.y << 5;
    int tx = threadIdx.x, ty = threadIdx.y;
    #pragma unroll
    for (int i = 0; i < 4; i++) {
        size_t o = (size_t)(rb + ty + i * 8) * C + cb + tx;
        th[ty + i * 8][tx] = sh_[o];
        tl[ty + i * 8][tx] = sl_[o];
    }
    __syncthreads();
    #pragma unroll
    for (int i = 0; i < 4; i++) {
        size_t o = (size_t)(cb + ty + i * 8) * R + rb + tx;
        dh[o] = th[tx][ty + i * 8];
        dl[o] = tl[tx][ty + i * 8];
    }
}

// ---------------------------------------------------------------------------
// adaLN embedding GEMV
// ---------------------------------------------------------------------------
__global__ void ada_gemv_kernel(const float* __restrict__ temb,
                                const float* __restrict__ Wi, const float* __restrict__ bi,
                                const float* __restrict__ Wt, const float* __restrict__ bt,
                                float* __restrict__ E)
{
    __shared__ float s[DIM];
    for (int i = threadIdx.x; i < DIM; i += 256) {
        float x = temb[i];
        s[i] = x / (1.f + expf(-x));
    }
    __syncthreads();
    int gcol = blockIdx.x * 256 + threadIdx.x;
    int which = gcol / 18432;
    int col = gcol - which * 18432;
    const float* W = which ? Wt : Wi;
    const float* b = which ? bt : bi;
    float acc = 0.f;
    for (int k = 0; k < DIM; k++)
        acc = fmaf(s[k], W[(size_t)k * 18432 + col], acc);
    E[gcol] = acc + b[col];
}

// ---------------------------------------------------------------------------
// LayerNorm + modulate -> bf16 hi/lo (feeds GEMM A operand)
// ---------------------------------------------------------------------------
__global__ void adaln_kernel(const float* xi, const float* xt,
                             const float* __restrict__ E, int off_shift, int off_scale,
                             bf16* oih, bf16* oil, bf16* oth, bf16* otl)
{
    __shared__ float shs[8], shq[8];
    int row = blockIdx.x;
    const float* x; bf16 *oh, *ol; const float* e;
    if (row < LI) {
        x = xi + (size_t)row * DIM;
        oh = oih + (size_t)row * DIM; ol = oil + (size_t)row * DIM; e = E;
    } else {
        int r = row - LI;
        x = xt + (size_t)r * DIM;
        oh = oth + (size_t)r * DIM; ol = otl + (size_t)r * DIM; e = E + 18432;
    }

    float sum = 0.f, sq = 0.f;
    for (int c = threadIdx.x; c < DIM; c += 256) {
        float v = x[c];
        sum += v; sq = fmaf(v, v, sq);
    }
    #pragma unroll
    for (int off = 16; off; off >>= 1) {
        sum += __shfl_xor_sync(0xffffffffu, sum, off);
        sq  += __shfl_xor_sync(0xffffffffu, sq,  off);
    }
    int w = threadIdx.x >> 5;
    if ((threadIdx.x & 31) == 0) { shs[w] = sum; shq[w] = sq; }
    __syncthreads();
    sum = 0.f; sq = 0.f;
    #pragma unroll
    for (int i = 0; i < 8; i++) { sum += shs[i]; sq += shq[i]; }
    float mean = sum * (1.f / DIM);
    float var  = sq * (1.f / DIM) - mean * mean;
    float rstd = rsqrtf(var + EPSV);
    for (int c = threadIdx.x; c < DIM; c += 256) {
        float v = (x[c] - mean) * rstd * (1.f + e[off_scale + c]) + e[off_shift + c];
        bf16 h, l; split_bf(v, h, l);
        oh[c] = h; ol[c] = l;
    }
}

// ---------------------------------------------------------------------------
// RMS-norm + RoPE + scatter: Q/K hi/lo row-major, V hi/lo NATURAL row-major
// ---------------------------------------------------------------------------
__global__ void rms_rope_kernel(const float* __restrict__ qkvt, const float* __restrict__ qkvi,
                                const float* __restrict__ rot,
                                const float* __restrict__ qs_i, const float* __restrict__ ks_i,
                                const float* __restrict__ qs_t, const float* __restrict__ ks_t,
                                bf16* Qh, bf16* Ql, bf16* Kh, bf16* Kl,
                                bf16* Vh, bf16* Vl)
{
    int token = blockIdx.x / Hn;
    int h     = blockIdx.x - token * Hn;
    int d     = threadIdx.x;

    const float* basep; const float* qs; const float* ks;
    if (token < LT) { basep = qkvt + (size_t)token * (3 * INNER);        qs = qs_t; ks = ks_t; }
    else            { basep = qkvi + (size_t)(token - LT) * (3 * INNER); qs = qs_i; ks = ks_i; }

    float qv = basep[            h * DH + d];
    float kv = basep[    INNER + h * DH + d];
    float vv = basep[2 * INNER + h * DH + d];

    float sq = qv * qv, sk = kv * kv;
    #pragma unroll
    for (int off = 16; off; off >>= 1) {
        sq += __shfl_xor_sync(0xffffffffu, sq, off);
        sk += __shfl_xor_sync(0xffffffffu, sk, off);
    }
    __shared__ float wq[4], wk[4];
    __shared__ float shq[DH], shk[DH];
    int w = d >> 5;
    if ((d & 31) == 0) { wq[w] = sq; wk[w] = sk; }
    __syncthreads();
    sq = wq[0] + wq[1] + wq[2] + wq[3];
    sk = wk[0] + wk[1] + wk[2] + wk[3];
    float qn = qv * rsqrtf(sq * (1.f / DH) + EPSV) * qs[d];
    float kn = kv * rsqrtf(sk * (1.f / DH) + EPSV) * ks[d];
    shq[d] = qn; shk[d] = kn;
    __syncthreads();

    int hh = d >> 1, j = d & 1;
    const float* f = &rot[(size_t)token * 256 + hh * 4 + j * 2];
    float f0 = f[0], f1 = f[1];
    float qo = f0 * shq[2 * hh] + f1 * shq[2 * hh + 1];
    float ko = f0 * shk[2 * hh] + f1 * shk[2 * hh + 1];

    size_t oidx = (size_t)token * INNER + h * DH + d;
    bf16 hq2, lq2, hk2, lk2, hv2, lv2;
    split_bf(qo, hq2, lq2);
    split_bf(ko, hk2, lk2);
    split_bf(vv, hv2, lv2);
    Qh[oidx] = hq2; Ql[oidx] = lq2;
    Kh[oidx] = hk2; Kl[oidx] = lk2;
    Vh[oidx] = hv2; Vl[oidx] = lv2;
}

// ---------------------------------------------------------------------------
// Row softmax over Lseq=4608 -> bf16 hi/lo probs (feeds O GEMM)
// ---------------------------------------------------------------------------
__global__ void softmax_kernel(const float* __restrict__ S, bf16* Ph, bf16* Pl)
{
    __shared__ float sh[8];
    const float* p = S + (size_t)blockIdx.x * Lseq;
    bf16* ph = Ph + (size_t)blockIdx.x * Lseq;
    bf16* pl = Pl + (size_t)blockIdx.x * Lseq;
    int tid = threadIdx.x;
    float v[18];
    float mx = -1e30f;
    #pragma unroll
    for (int i = 0; i < 18; i++) { v[i] = p[i * 256 + tid]; mx = fmaxf(mx, v[i]); }
    #pragma unroll
    for (int off = 16; off; off >>= 1) mx = fmaxf(mx, __shfl_xor_sync(0xffffffffu, mx, off));
    int w = tid >> 5;
    if ((tid & 31) == 0) sh[w] = mx;
    __syncthreads();
    mx = sh[0];
    #pragma unroll
    for (int i = 1; i < 8; i++) mx = fmaxf(mx, sh[i]);
    __syncthreads();
    float sum = 0.f;
    #pragma unroll
    for (int i = 0; i < 18; i++) { v[i] = expf(v[i] - mx); sum += v[i]; }
    #pragma unroll
    for (int off = 16; off; off >>= 1) sum += __shfl_xor_sync(0xffffffffu, sum, off);
    if ((tid & 31) == 0) sh[w] = sum;
    __syncthreads();
    sum = 0.f;
    #pragma unroll
    for (int i = 0; i < 8; i++) sum += sh[i];
    float inv = 1.f / sum;
    #pragma unroll
    for (int i = 0; i < 18; i++) {
        bf16 h, l; split_bf(v[i] * inv, h, l);
        ph[i * 256 + tid] = h; pl[i * 256 + tid] = l;
    }
}

// ---------------------------------------------------------------------------
// Launch
// ---------------------------------------------------------------------------
extern "C" void kernel_launch(void* const* d_in, const int* in_sizes, int n_in,
                              void* d_out, int out_size)
{
    const float* hidden  = (const float*)d_in[0];
    const float* enc     = (const float*)d_in[1];
    const float* temb    = (const float*)d_in[2];
    const float* rot     = (const float*)d_in[3];
    const float* W_iada  = (const float*)d_in[4];
    const float* b_iada  = (const float*)d_in[5];
    const float* W_tada  = (const float*)d_in[6];
    const float* b_tada  = (const float*)d_in[7];
    const float* W_iqkv  = (const float*)d_in[8];
    const float* W_eqkv  = (const float*)d_in[9];
    const float* W_iproj = (const float*)d_in[10];
    const float* b_iproj = (const float*)d_in[11];
    const float* W_eproj = (const float*)d_in[12];
    const float* b_eproj = (const float*)d_in[13];
    const float* q_scale  = (const float*)d_in[14];
    const float* k_scale  = (const float*)d_in[15];
    const float* eq_scale = (const float*)d_in[16];
    const float* ek_scale = (const float*)d_in[17];
    const float* W_imlp1 = (const float*)d_in[18];
    const float* b_imlp1 = (const float*)d_in[19];
    const float* W_imlp2 = (const float*)d_in[20];
    const float* b_imlp2 = (const float*)d_in[21];
    const float* W_tmlp1 = (const float*)d_in[22];
    const float* b_tmlp1 = (const float*)d_in[23];
    const float* W_tmlp2 = (const float*)d_in[24];
    const float* b_tmlp2 = (const float*)d_in[25];

    float* out = (float*)d_out;
    float* hs = out;
    float* es = out + (size_t)LI * DIM;

    float *E, *QKVI, *QKVT, *Sb;
    bf16 *NHh, *NHl, *NEh, *NEl, *Qh, *Ql, *Kh, *Kl, *Vnh, *Vnl, *VTh, *VTl;
    bf16 *Ph, *Pl, *Oh, *Ol, *FFIh, *FFIl, *FFTh, *FFTl;
    bf16 *Wiqkvh, *Wiqkvl, *Weqkvh, *Weqkvl, *Wiprjh, *Wiprjl, *Weprjh, *Weprjl;
    bf16 *Wim1h, *Wim1l, *Wtm1h, *Wtm1l, *Wim2h, *Wim2l, *Wtm2h, *Wtm2l;

    cudaGetSymbolAddress((void**)&E,     g_E);
    cudaGetSymbolAddress((void**)&QKVI,  g_QKVI);
    cudaGetSymbolAddress((void**)&QKVT,  g_QKVT);
    cudaGetSymbolAddress((void**)&Sb,    g_S);
    cudaGetSymbolAddress((void**)&NHh,   g_NHhi);  cudaGetSymbolAddress((void**)&NHl, g_NHlo);
    cudaGetSymbolAddress((void**)&NEh,   g_NEhi);  cudaGetSymbolAddress((void**)&NEl, g_NElo);
    cudaGetSymbolAddress((void**)&Qh,    g_Qhi);   cudaGetSymbolAddress((void**)&Ql,  g_Qlo);
    cudaGetSymbolAddress((void**)&Kh,    g_Khi);   cudaGetSymbolAddress((void**)&Kl,  g_Klo);
    cudaGetSymbolAddress((void**)&Vnh,   g_Vnh);   cudaGetSymbolAddress((void**)&Vnl, g_Vnl);
    cudaGetSymbolAddress((void**)&VTh,   g_VThi);  cudaGetSymbolAddress((void**)&VTl, g_VTlo);
    cudaGetSymbolAddress((void**)&Ph,    g_Phi);   cudaGetSymbolAddress((void**)&Pl,  g_Plo);
    cudaGetSymbolAddress((void**)&Oh,    g_Ohi);   cudaGetSymbolAddress((void**)&Ol,  g_Olo);
    cudaGetSymbolAddress((void**)&FFIh,  g_FFIhi); cudaGetSymbolAddress((void**)&FFIl, g_FFIlo);
    cudaGetSymbolAddress((void**)&FFTh,  g_FFThi); cudaGetSymbolAddress((void**)&FFTl, g_FFTlo);
    cudaGetSymbolAddress((void**)&Wiqkvh, g_Wiqkv_h); cudaGetSymbolAddress((void**)&Wiqkvl, g_Wiqkv_l);
    cudaGetSymbolAddress((void**)&Weqkvh, g_Weqkv_h); cudaGetSymbolAddress((void**)&Weqkvl, g_Weqkv_l);
    cudaGetSymbolAddress((void**)&Wiprjh, g_Wiprj_h); cudaGetSymbolAddress((void**)&Wiprjl, g_Wiprj_l);
    cudaGetSymbolAddress((void**)&Weprjh, g_Weprj_h); cudaGetSymbolAddress((void**)&Weprjl, g_Weprj_l);
    cudaGetSymbolAddress((void**)&Wim1h,  g_Wim1_h);  cudaGetSymbolAddress((void**)&Wim1l,  g_Wim1_l);
    cudaGetSymbolAddress((void**)&Wtm1h,  g_Wtm1_h);  cudaGetSymbolAddress((void**)&Wtm1l,  g_Wtm1_l);
    cudaGetSymbolAddress((void**)&Wim2h,  g_Wim2_h);  cudaGetSymbolAddress((void**)&Wim2l,  g_Wim2_l);
    cudaGetSymbolAddress((void**)&Wtm2h,  g_Wtm2_h);  cudaGetSymbolAddress((void**)&Wtm2l,  g_Wtm2_l);

    const float* Ei = E;
    const float* Et = E + 18432;

    cudaFuncSetAttribute(gemm_bf3<0>, cudaFuncAttributeMaxDynamicSharedMemorySize, SMEMSZ);
    cudaFuncSetAttribute(gemm_bf3<1>, cudaFuncAttributeMaxDynamicSharedMemorySize, SMEMSZ);
    cudaFuncSetAttribute(gemm_bf3<2>, cudaFuncAttributeMaxDynamicSharedMemorySize, SMEMSZ);
    cudaFuncSetAttribute(gemm_bf3<3>, cudaFuncAttributeMaxDynamicSharedMemorySize, SMEMSZ);

    dim3 tb(32, 8);
    transpose_kernel<<<dim3(9216 / 32, DIM / 32), tb>>>(W_iqkv,  Wiqkvh, Wiqkvl, DIM,  9216);
    transpose_kernel<<<dim3(9216 / 32, DIM / 32), tb>>>(W_eqkv,  Weqkvh, Weqkvl, DIM,  9216);
    transpose_kernel<<<dim3(DIM / 32, INNER / 32), tb>>>(W_iproj, Wiprjh, Wiprjl, INNER, DIM);
    transpose_kernel<<<dim3(DIM / 32, INNER / 32), tb>>>(W_eproj, Weprjh, Weprjl, INNER, DIM);
    transpose_kernel<<<dim3(MLPD / 32, DIM / 32), tb>>>(W_imlp1, Wim1h, Wim1l, DIM,  MLPD);
    transpose_kernel<<<dim3(MLPD / 32, DIM / 32), tb>>>(W_tmlp1, Wtm1h, Wtm1l, DIM,  MLPD);
    transpose_kernel<<<dim3(DIM / 32, MLPD / 32), tb>>>(W_imlp2, Wim2h, Wim2l, MLPD, DIM);
    transpose_kernel<<<dim3(DIM / 32, MLPD / 32), tb>>>(W_tmlp2, Wtm2h, Wtm2l, MLPD, DIM);

    // 1. adaLN embeddings
    ada_gemv_kernel<<<144, 256>>>(temb, W_iada, b_iada, W_tada, b_tada, E);

    // 2. LN + modulate (msa)
    adaln_kernel<<<LI + LT, 256>>>(hidden, enc, E, 0, 3072, NHh, NHl, NEh, NEl);

    // 3. QKV projections (img + txt in one launch) -> fp32
    {
        GemmSet si = { NHh, NHl, Wiqkvh, Wiqkvl, QKVI, nullptr, nullptr,
                       nullptr, nullptr, nullptr };
        GemmSet st = { NEh, NEl, Weqkvh, Weqkvl, QKVT, nullptr, nullptr,
                       nullptr, nullptr, nullptr };
        gemm_bf3<0><<<dim3(9216 / 128, (LI + LT) / 128), 256, SMEMSZ>>>(
            si, st, LI, 9216, DIM, 1.f);
    }

    // 4. RMS + RoPE + concat scatter (V natural), then coalesced V transpose
    rms_rope_kernel<<<Lseq * Hn, 128>>>(QKVT, QKVI, rot, q_scale, k_scale, eq_scale, ek_scale,
                                        Qh, Ql, Kh, Kl, Vnh, Vnl);
    transpose_bf_kernel<<<dim3(INNER / 32, Lseq / 32), tb>>>(Vnh, Vnl, VTh, VTl, Lseq, INNER);

    // 5. S = (Q K^T) / sqrt(DH) -> fp32
    {
        GemmSet ss = { Qh, Ql, Kh, Kl, Sb, nullptr, nullptr, nullptr, nullptr, nullptr };
        gemm_bf3<0><<<dim3(Lseq / 128, Lseq / 128), 256, SMEMSZ>>>(
            ss, ss, Lseq, Lseq, INNER, 0.08838834764831843f);
    }

    // 6. softmax -> P hi/lo
    softmax_kernel<<<Lseq, 256>>>(Sb, Ph, Pl);

    // 7. O = P V -> hi/lo
    {
        GemmSet so = { Ph, Pl, VTh, VTl, nullptr, Oh, Ol, nullptr, nullptr, nullptr };
        gemm_bf3<1><<<dim3(INNER / 128, Lseq / 128), 256, SMEMSZ>>>(
            so, so, Lseq, INNER, Lseq, 1.f);
    }

    // 8. output projections (img + txt fused) with gated residual -> d_out
    {
        GemmSet si = { Oh + (size_t)LT * INNER, Ol + (size_t)LT * INNER,
                       Wiprjh, Wiprjl, hs, nullptr, nullptr,
                       b_iproj, Ei + 6144, hidden };
        GemmSet st = { Oh, Ol, Weprjh, Weprjl, es, nullptr, nullptr,
                       b_eproj, Et + 6144, enc };
        gemm_bf3<2><<<dim3(DIM / 128, (LI + LT) / 128), 256, SMEMSZ>>>(
            si, st, LI, DIM, INNER, 1.f);
    }

    // 9. LN + modulate (mlp)
    adaln_kernel<<<LI + LT, 256>>>(hs, es, E, 9216, 12288, NHh, NHl, NEh, NEl);

    // 10. MLP1 + fused gelu (img + txt fused) -> hi/lo
    {
        GemmSet si = { NHh, NHl, Wim1h, Wim1l, nullptr, FFIh, FFIl,
                       b_imlp1, nullptr, nullptr };
        GemmSet st = { NEh, NEl, Wtm1h, Wtm1l, nullptr, FFTh, FFTl,
                       b_tmlp1, nullptr, nullptr };
        gemm_bf3<3><<<dim3(MLPD / 128, (LI + LT) / 128), 256, SMEMSZ>>>(
            si, st, LI, MLPD, DIM, 1.f);
    }

    // 11. MLP2 (img + txt fused) with gated residual (in-place on d_out)
    {
        GemmSet si = { FFIh, FFIl, Wim2h, Wim2l, hs, nullptr, nullptr,
                       b_imlp2, Ei + 15360, hs };
        GemmSet st = { FFTh, FFTl, Wtm2h, Wtm2l, es, nullptr, nullptr,
                       b_tmlp2, Et + 15360, es };
        gemm_bf3<2><<<dim3(DIM / 128, (LI + LT) / 128), 256, SMEMSZ>>>(
            si, st, LI, DIM, MLPD, 1.f);
    }
}

// round 10
// speedup vs baseline: 1.2583x; 1.0583x over previous
#include <cuda_runtime.h>
#include <cuda_bf16.h>
#include <math.h>

#define DIM   3072
#define Hn    24
#define DH    128
#define INNER 3072
#define LI    4096
#define LT    512
#define Lseq  (LI + LT)        // 4608
#define MLPD  12288
#define EPSV  1e-6f

// GEMM config: CTA tile 128x128, 4 warps (2x2), warp tile 64x64, KCH=32,
// 2 stages, 2 CTAs/SM (128 threads/CTA -> up to 256 regs/thread).
#define KCH   32
#define SH    40                           // row stride in halves
#define PART_HALVES (128 * SH)             // 5120 halves = 10240 B
#define STAGE_BYTES (4 * PART_HALVES * 2)  // 40960
#define SMEMSZ (2 * STAGE_BYTES)           // 81920

typedef __nv_bfloat16 bf16;

// ---------------------------------------------------------------------------
// Scratch (device globals; allocation-free per harness rules)
// ---------------------------------------------------------------------------
__device__ float g_E[2 * 18432];
__device__ bf16  g_NHhi[(size_t)LI * DIM],  g_NHlo[(size_t)LI * DIM];
__device__ bf16  g_NEhi[(size_t)LT * DIM],  g_NElo[(size_t)LT * DIM];
__device__ float g_QKVI[(size_t)LI * 3 * INNER];
__device__ float g_QKVT[(size_t)LT * 3 * INNER];
__device__ bf16  g_Qhi[(size_t)Lseq * INNER], g_Qlo[(size_t)Lseq * INNER];
__device__ bf16  g_Khi[(size_t)Lseq * INNER], g_Klo[(size_t)Lseq * INNER];
__device__ bf16  g_Vnh[(size_t)Lseq * INNER],  g_Vnl[(size_t)Lseq * INNER];   // natural
__device__ bf16  g_VThi[(size_t)INNER * Lseq], g_VTlo[(size_t)INNER * Lseq];  // transposed
__device__ float g_S[(size_t)Lseq * Lseq];
__device__ bf16  g_Phi[(size_t)Lseq * Lseq], g_Plo[(size_t)Lseq * Lseq];
__device__ bf16  g_Ohi[(size_t)Lseq * INNER], g_Olo[(size_t)Lseq * INNER];
__device__ bf16  g_FFIhi[(size_t)LI * MLPD], g_FFIlo[(size_t)LI * MLPD];
__device__ bf16  g_FFThi[(size_t)LT * MLPD], g_FFTlo[(size_t)LT * MLPD];
// transposed (N,K) weights, bf16 hi/lo split
__device__ bf16 g_Wiqkv_h[(size_t)9216 * DIM],  g_Wiqkv_l[(size_t)9216 * DIM];
__device__ bf16 g_Weqkv_h[(size_t)9216 * DIM],  g_Weqkv_l[(size_t)9216 * DIM];
__device__ bf16 g_Wiprj_h[(size_t)DIM * INNER], g_Wiprj_l[(size_t)DIM * INNER];
__device__ bf16 g_Weprj_h[(size_t)DIM * INNER], g_Weprj_l[(size_t)DIM * INNER];
__device__ bf16 g_Wim1_h[(size_t)MLPD * DIM],   g_Wim1_l[(size_t)MLPD * DIM];
__device__ bf16 g_Wtm1_h[(size_t)MLPD * DIM],   g_Wtm1_l[(size_t)MLPD * DIM];
__device__ bf16 g_Wim2_h[(size_t)DIM * MLPD],   g_Wim2_l[(size_t)DIM * MLPD];
__device__ bf16 g_Wtm2_h[(size_t)DIM * MLPD],   g_Wtm2_l[(size_t)DIM * MLPD];

// ---------------------------------------------------------------------------
// Helpers
// ---------------------------------------------------------------------------
__device__ __forceinline__ void split_bf(float x, bf16& h, bf16& l) {
    h = __float2bfloat16(x);
    l = __float2bfloat16(x - __bfloat162float(h));
}

__device__ __forceinline__ unsigned s2u(const void* p) {
    unsigned a;
    asm("{ .reg .u64 t; cvta.to.shared.u64 t, %1; cvt.u32.u64 %0, t; }" : "=r"(a) : "l"(p));
    return a;
}

__device__ __forceinline__ void mma_bf16(float* c, const unsigned* a, const unsigned* b) {
    asm volatile(
        "mma.sync.aligned.m16n8k16.row.col.f32.bf16.bf16.f32 "
        "{%0,%1,%2,%3}, {%4,%5,%6,%7}, {%8,%9}, {%0,%1,%2,%3};"
        : "+f"(c[0]), "+f"(c[1]), "+f"(c[2]), "+f"(c[3])
        : "r"(a[0]), "r"(a[1]), "r"(a[2]), "r"(a[3]), "r"(b[0]), "r"(b[1]));
}

__device__ __forceinline__ void ldsm4(unsigned& r0, unsigned& r1, unsigned& r2, unsigned& r3,
                                      unsigned addr) {
    asm volatile("ldmatrix.sync.aligned.m8n8.x4.shared.b16 {%0,%1,%2,%3}, [%4];"
                 : "=r"(r0), "=r"(r1), "=r"(r2), "=r"(r3) : "r"(addr));
}

// Per-problem pointer pack (img+txt fused launches)
struct GemmSet {
    const bf16 *Ah, *Al, *Bh, *Bl;
    float* Cf;
    bf16 *Chi, *Clo;
    const float *bias, *gate, *resid;
};

// ---------------------------------------------------------------------------
// bf16x3 split GEMM: C = epi(A @ B^T). Two problem sets share one launch.
// acc += Ah*Bh + Ah*Bl + Al*Bh   (fp32 accumulate; lo*lo dropped)
// 128x128 CTA tile, 4 warps (2x2), warp tile 64x64, KCH=32, double-buffered,
// ldmatrix.x4, 2 CTAs/SM.
// EPI: 0 -> Cf = scale*acc ; 1 -> split(acc) ; 2 -> resid + gate*(acc+bias) ;
//      3 -> split(gelu(acc+bias))
// ---------------------------------------------------------------------------
template<int EPI>
__global__ void __launch_bounds__(128, 2)
gemm_bf3(GemmSet s0, GemmSet s1, int M0, int N, int K, float scale)
{
    extern __shared__ char smem[];
    const int tid  = threadIdx.x;
    const int wid  = tid >> 5, lane = tid & 31;
    const int g    = lane >> 2, t = lane & 3;
    const int wm   = wid & 1;          // 2 warp rows x 64
    const int wn   = wid >> 1;         // 2 warp cols x 64
    int row0 = blockIdx.y * 128;
    const GemmSet s = (row0 < M0) ? s0 : s1;
    if (row0 >= M0) row0 -= M0;
    const int col0 = blockIdx.x * 128;
    const int T    = K >> 5;

    const unsigned sbase = s2u(smem);
    const bf16* gp[4] = { s.Ah + (size_t)row0 * K, s.Al + (size_t)row0 * K,
                          s.Bh + (size_t)col0 * K, s.Bl + (size_t)col0 * K };

    // ldmatrix per-lane offsets (bytes within a part)
    const int lr = lane & 7;
    const unsigned aoff = ((unsigned)(wm * 64 + ((lane >> 3) & 1) * 8 + lr) * SH
                           + (unsigned)(lane >> 4) * 8) * 2u;
    const unsigned boff = ((unsigned)(wn * 64 + (lane >> 4) * 8 + lr) * SH
                           + (unsigned)((lane >> 3) & 1) * 8) * 2u;

    auto load_stage = [&](int st_, int kc) {
        unsigned st = sbase + (unsigned)st_ * STAGE_BYTES;
        #pragma unroll
        for (int p = 0; p < 4; p++) {          // 4 parts x 512 chunks
            #pragma unroll
            for (int i = 0; i < 4; i++) {      // 128 threads -> 4 iters
                int idx = (i << 7) + tid;
                int r = idx >> 2;
                int c = (idx & 3) << 3;
                unsigned sa = st + (unsigned)p * (PART_HALVES * 2)
                                 + (unsigned)(r * (SH * 2) + c * 2);
                asm volatile("cp.async.cg.shared.global [%0], [%1], 16;"
                             :: "r"(sa), "l"(gp[p] + (size_t)r * K + kc + c) : "memory");
            }
        }
    };

    float acc[4][8][4];
    #pragma unroll
    for (int i = 0; i < 4; i++)
        #pragma unroll
        for (int j = 0; j < 8; j++)
            #pragma unroll
            for (int q = 0; q < 4; q++) acc[i][j][q] = 0.f;

    load_stage(0, 0);
    asm volatile("cp.async.commit_group;" ::: "memory");

    for (int kt = 0; kt < T; kt++) {
        if (kt + 1 < T) {
            load_stage((kt + 1) & 1, (kt + 1) * KCH);
            asm volatile("cp.async.commit_group;" ::: "memory");
            asm volatile("cp.async.wait_group 1;" ::: "memory");
        } else {
            asm volatile("cp.async.wait_group 0;" ::: "memory");
        }
        __syncthreads();

        const unsigned stb = sbase + (unsigned)(kt & 1) * STAGE_BYTES;
        const unsigned Ahb = stb;
        const unsigned Alb = stb + PART_HALVES * 2;
        const unsigned Bhb = stb + 2 * PART_HALVES * 2;
        const unsigned Blb = stb + 3 * PART_HALVES * 2;

        #pragma unroll
        for (int ks = 0; ks < 2; ks++) {
            const unsigned kb = (unsigned)ks * 32u;
            unsigned bh[8][2], bl[8][2], af[4][4];
            #pragma unroll
            for (int p = 0; p < 4; p++) {
                unsigned off = boff + (unsigned)p * (16 * SH * 2) + kb;
                ldsm4(bh[2*p][0], bh[2*p][1], bh[2*p+1][0], bh[2*p+1][1], Bhb + off);
                ldsm4(bl[2*p][0], bl[2*p][1], bl[2*p+1][0], bl[2*p+1][1], Blb + off);
            }
            #pragma unroll
            for (int mt = 0; mt < 4; mt++)
                ldsm4(af[mt][0], af[mt][1], af[mt][2], af[mt][3],
                      Ahb + aoff + (unsigned)mt * (16 * SH * 2) + kb);
            #pragma unroll
            for (int mt = 0; mt < 4; mt++)
                #pragma unroll
                for (int nt = 0; nt < 8; nt++)
                    mma_bf16(acc[mt][nt], af[mt], bh[nt]);
            #pragma unroll
            for (int mt = 0; mt < 4; mt++)
                #pragma unroll
                for (int nt = 0; nt < 8; nt++)
                    mma_bf16(acc[mt][nt], af[mt], bl[nt]);
            #pragma unroll
            for (int mt = 0; mt < 4; mt++)
                ldsm4(af[mt][0], af[mt][1], af[mt][2], af[mt][3],
                      Alb + aoff + (unsigned)mt * (16 * SH * 2) + kb);
            #pragma unroll
            for (int mt = 0; mt < 4; mt++)
                #pragma unroll
                for (int nt = 0; nt < 8; nt++)
                    mma_bf16(acc[mt][nt], af[mt], bh[nt]);
        }
        __syncthreads();
    }

    // epilogue
    #pragma unroll
    for (int mt = 0; mt < 4; mt++) {
        #pragma unroll
        for (int half = 0; half < 2; half++) {
            int row = row0 + wm * 64 + mt * 16 + g + half * 8;
            #pragma unroll
            for (int nt = 0; nt < 8; nt++) {
                int col = col0 + wn * 64 + nt * 8 + t * 2;
                size_t off = (size_t)row * N + col;
                float v0 = acc[mt][nt][half * 2];
                float v1 = acc[mt][nt][half * 2 + 1];
                if (EPI == 0) {
                    s.Cf[off]     = v0 * scale;
                    s.Cf[off + 1] = v1 * scale;
                } else if (EPI == 2) {
                    s.Cf[off]     = s.resid[off]     + s.gate[col]     * (v0 + s.bias[col]);
                    s.Cf[off + 1] = s.resid[off + 1] + s.gate[col + 1] * (v1 + s.bias[col + 1]);
                } else {
                    if (EPI == 3) {
                        float u0 = v0 + s.bias[col], u1 = v1 + s.bias[col + 1];
                        v0 = 0.5f * u0 * (1.f + tanhf(0.7978845608028654f *
                                 (u0 + 0.044715f * u0 * u0 * u0)));
                        v1 = 0.5f * u1 * (1.f + tanhf(0.7978845608028654f *
                                 (u1 + 0.044715f * u1 * u1 * u1)));
                    }
                    bf16 h0, l0, h1, l1;
                    split_bf(v0, h0, l0);
                    split_bf(v1, h1, l1);
                    *(__nv_bfloat162*)(s.Chi + off) = __nv_bfloat162(h0, h1);
                    *(__nv_bfloat162*)(s.Clo + off) = __nv_bfloat162(l0, l1);
                }
            }
        }
    }
}

// ---------------------------------------------------------------------------
// Weight transpose [K,N] -> [N,K], bf16 hi/lo split
// ---------------------------------------------------------------------------
__global__ void transpose_kernel(const float* __restrict__ src,
                                 bf16* __restrict__ dh, bf16* __restrict__ dl,
                                 int K, int N)
{
    __shared__ float t[32][33];
    int nb = blockIdx.x << 5, kb = blockIdx.y << 5;
    int tx = threadIdx.x, ty = threadIdx.y;
    #pragma unroll
    for (int i = 0; i < 4; i++)
        t[ty + i * 8][tx] = src[(size_t)(kb + ty + i * 8) * N + nb + tx];
    __syncthreads();
    #pragma unroll
    for (int i = 0; i < 4; i++) {
        bf16 h, l;
        split_bf(t[tx][ty + i * 8], h, l);
        size_t o = (size_t)(nb + ty + i * 8) * K + kb + tx;
        dh[o] = h; dl[o] = l;
    }
}

// ---------------------------------------------------------------------------
// bf16 pair transpose: [R,C] -> [C,R]  (for V -> V^T)
// ---------------------------------------------------------------------------
__global__ void transpose_bf_kernel(const bf16* __restrict__ sh_, const bf16* __restrict__ sl_,
                                    bf16* __restrict__ dh, bf16* __restrict__ dl,
                                    int R, int C)
{
    __shared__ bf16 th[32][34], tl[32][34];
    int cb = blockIdx.x << 5, rb = blockIdx.y << 5;
    int tx = threadIdx.x, ty = threadIdx.y;
    #pragma unroll
    for (int i = 0; i < 4; i++) {
        size_t o = (size_t)(rb + ty + i * 8) * C + cb + tx;
        th[ty + i * 8][tx] = sh_[o];
        tl[ty + i * 8][tx] = sl_[o];
    }
    __syncthreads();
    #pragma unroll
    for (int i = 0; i < 4; i++) {
        size_t o = (size_t)(cb + ty + i * 8) * R + rb + tx;
        dh[o] = th[tx][ty + i * 8];
        dl[o] = tl[tx][ty + i * 8];
    }
}

// ---------------------------------------------------------------------------
// adaLN embedding GEMV
// ---------------------------------------------------------------------------
__global__ void ada_gemv_kernel(const float* __restrict__ temb,
                                const float* __restrict__ Wi, const float* __restrict__ bi,
                                const float* __restrict__ Wt, const float* __restrict__ bt,
                                float* __restrict__ E)
{
    __shared__ float s[DIM];
    for (int i = threadIdx.x; i < DIM; i += 256) {
        float x = temb[i];
        s[i] = x / (1.f + expf(-x));
    }
    __syncthreads();
    int gcol = blockIdx.x * 256 + threadIdx.x;
    int which = gcol / 18432;
    int col = gcol - which * 18432;
    const float* W = which ? Wt : Wi;
    const float* b = which ? bt : bi;
    float acc = 0.f;
    for (int k = 0; k < DIM; k++)
        acc = fmaf(s[k], W[(size_t)k * 18432 + col], acc);
    E[gcol] = acc + b[col];
}

// ---------------------------------------------------------------------------
// LayerNorm + modulate -> bf16 hi/lo (feeds GEMM A operand)
// ---------------------------------------------------------------------------
__global__ void adaln_kernel(const float* xi, const float* xt,
                             const float* __restrict__ E, int off_shift, int off_scale,
                             bf16* oih, bf16* oil, bf16* oth, bf16* otl)
{
    __shared__ float shs[8], shq[8];
    int row = blockIdx.x;
    const float* x; bf16 *oh, *ol; const float* e;
    if (row < LI) {
        x = xi + (size_t)row * DIM;
        oh = oih + (size_t)row * DIM; ol = oil + (size_t)row * DIM; e = E;
    } else {
        int r = row - LI;
        x = xt + (size_t)r * DIM;
        oh = oth + (size_t)r * DIM; ol = otl + (size_t)r * DIM; e = E + 18432;
    }

    float sum = 0.f, sq = 0.f;
    for (int c = threadIdx.x; c < DIM; c += 256) {
        float v = x[c];
        sum += v; sq = fmaf(v, v, sq);
    }
    #pragma unroll
    for (int off = 16; off; off >>= 1) {
        sum += __shfl_xor_sync(0xffffffffu, sum, off);
        sq  += __shfl_xor_sync(0xffffffffu, sq,  off);
    }
    int w = threadIdx.x >> 5;
    if ((threadIdx.x & 31) == 0) { shs[w] = sum; shq[w] = sq; }
    __syncthreads();
    sum = 0.f; sq = 0.f;
    #pragma unroll
    for (int i = 0; i < 8; i++) { sum += shs[i]; sq += shq[i]; }
    float mean = sum * (1.f / DIM);
    float var  = sq * (1.f / DIM) - mean * mean;
    float rstd = rsqrtf(var + EPSV);
    for (int c = threadIdx.x; c < DIM; c += 256) {
        float v = (x[c] - mean) * rstd * (1.f + e[off_scale + c]) + e[off_shift + c];
        bf16 h, l; split_bf(v, h, l);
        oh[c] = h; ol[c] = l;
    }
}

// ---------------------------------------------------------------------------
// RMS-norm + RoPE + scatter: Q/K hi/lo row-major, V hi/lo NATURAL row-major
// ---------------------------------------------------------------------------
__global__ void rms_rope_kernel(const float* __restrict__ qkvt, const float* __restrict__ qkvi,
                                const float* __restrict__ rot,
                                const float* __restrict__ qs_i, const float* __restrict__ ks_i,
                                const float* __restrict__ qs_t, const float* __restrict__ ks_t,
                                bf16* Qh, bf16* Ql, bf16* Kh, bf16* Kl,
                                bf16* Vh, bf16* Vl)
{
    int token = blockIdx.x / Hn;
    int h     = blockIdx.x - token * Hn;
    int d     = threadIdx.x;

    const float* basep; const float* qs; const float* ks;
    if (token < LT) { basep = qkvt + (size_t)token * (3 * INNER);        qs = qs_t; ks = ks_t; }
    else            { basep = qkvi + (size_t)(token - LT) * (3 * INNER); qs = qs_i; ks = ks_i; }

    float qv = basep[            h * DH + d];
    float kv = basep[    INNER + h * DH + d];
    float vv = basep[2 * INNER + h * DH + d];

    float sq = qv * qv, sk = kv * kv;
    #pragma unroll
    for (int off = 16; off; off >>= 1) {
        sq += __shfl_xor_sync(0xffffffffu, sq, off);
        sk += __shfl_xor_sync(0xffffffffu, sk, off);
    }
    __shared__ float wq[4], wk[4];
    __shared__ float shq[DH], shk[DH];
    int w = d >> 5;
    if ((d & 31) == 0) { wq[w] = sq; wk[w] = sk; }
    __syncthreads();
    sq = wq[0] + wq[1] + wq[2] + wq[3];
    sk = wk[0] + wk[1] + wk[2] + wk[3];
    float qn = qv * rsqrtf(sq * (1.f / DH) + EPSV) * qs[d];
    float kn = kv * rsqrtf(sk * (1.f / DH) + EPSV) * ks[d];
    shq[d] = qn; shk[d] = kn;
    __syncthreads();

    int hh = d >> 1, j = d & 1;
    const float* f = &rot[(size_t)token * 256 + hh * 4 + j * 2];
    float f0 = f[0], f1 = f[1];
    float qo = f0 * shq[2 * hh] + f1 * shq[2 * hh + 1];
    float ko = f0 * shk[2 * hh] + f1 * shk[2 * hh + 1];

    size_t oidx = (size_t)token * INNER + h * DH + d;
    bf16 hq2, lq2, hk2, lk2, hv2, lv2;
    split_bf(qo, hq2, lq2);
    split_bf(ko, hk2, lk2);
    split_bf(vv, hv2, lv2);
    Qh[oidx] = hq2; Ql[oidx] = lq2;
    Kh[oidx] = hk2; Kl[oidx] = lk2;
    Vh[oidx] = hv2; Vl[oidx] = lv2;
}

// ---------------------------------------------------------------------------
// Row softmax over Lseq=4608 -> bf16 hi/lo probs (feeds O GEMM)
// ---------------------------------------------------------------------------
__global__ void softmax_kernel(const float* __restrict__ S, bf16* Ph, bf16* Pl)
{
    __shared__ float sh[8];
    const float* p = S + (size_t)blockIdx.x * Lseq;
    bf16* ph = Ph + (size_t)blockIdx.x * Lseq;
    bf16* pl = Pl + (size_t)blockIdx.x * Lseq;
    int tid = threadIdx.x;
    float v[18];
    float mx = -1e30f;
    #pragma unroll
    for (int i = 0; i < 18; i++) { v[i] = p[i * 256 + tid]; mx = fmaxf(mx, v[i]); }
    #pragma unroll
    for (int off = 16; off; off >>= 1) mx = fmaxf(mx, __shfl_xor_sync(0xffffffffu, mx, off));
    int w = tid >> 5;
    if ((tid & 31) == 0) sh[w] = mx;
    __syncthreads();
    mx = sh[0];
    #pragma unroll
    for (int i = 1; i < 8; i++) mx = fmaxf(mx, sh[i]);
    __syncthreads();
    float sum = 0.f;
    #pragma unroll
    for (int i = 0; i < 18; i++) { v[i] = expf(v[i] - mx); sum += v[i]; }
    #pragma unroll
    for (int off = 16; off; off >>= 1) sum += __shfl_xor_sync(0xffffffffu, sum, off);
    if ((tid & 31) == 0) sh[w] = sum;
    __syncthreads();
    sum = 0.f;
    #pragma unroll
    for (int i = 0; i < 8; i++) sum += sh[i];
    float inv = 1.f / sum;
    #pragma unroll
    for (int i = 0; i < 18; i++) {
        bf16 h, l; split_bf(v[i] * inv, h, l);
        ph[i * 256 + tid] = h; pl[i * 256 + tid] = l;
    }
}

// ---------------------------------------------------------------------------
// Launch
// ---------------------------------------------------------------------------
extern "C" void kernel_launch(void* const* d_in, const int* in_sizes, int n_in,
                              void* d_out, int out_size)
{
    const float* hidden  = (const float*)d_in[0];
    const float* enc     = (const float*)d_in[1];
    const float* temb    = (const float*)d_in[2];
    const float* rot     = (const float*)d_in[3];
    const float* W_iada  = (const float*)d_in[4];
    const float* b_iada  = (const float*)d_in[5];
    const float* W_tada  = (const float*)d_in[6];
    const float* b_tada  = (const float*)d_in[7];
    const float* W_iqkv  = (const float*)d_in[8];
    const float* W_eqkv  = (const float*)d_in[9];
    const float* W_iproj = (const float*)d_in[10];
    const float* b_iproj = (const float*)d_in[11];
    const float* W_eproj = (const float*)d_in[12];
    const float* b_eproj = (const float*)d_in[13];
    const float* q_scale  = (const float*)d_in[14];
    const float* k_scale  = (const float*)d_in[15];
    const float* eq_scale = (const float*)d_in[16];
    const float* ek_scale = (const float*)d_in[17];
    const float* W_imlp1 = (const float*)d_in[18];
    const float* b_imlp1 = (const float*)d_in[19];
    const float* W_imlp2 = (const float*)d_in[20];
    const float* b_imlp2 = (const float*)d_in[21];
    const float* W_tmlp1 = (const float*)d_in[22];
    const float* b_tmlp1 = (const float*)d_in[23];
    const float* W_tmlp2 = (const float*)d_in[24];
    const float* b_tmlp2 = (const float*)d_in[25];

    float* out = (float*)d_out;
    float* hs = out;
    float* es = out + (size_t)LI * DIM;

    float *E, *QKVI, *QKVT, *Sb;
    bf16 *NHh, *NHl, *NEh, *NEl, *Qh, *Ql, *Kh, *Kl, *Vnh, *Vnl, *VTh, *VTl;
    bf16 *Ph, *Pl, *Oh, *Ol, *FFIh, *FFIl, *FFTh, *FFTl;
    bf16 *Wiqkvh, *Wiqkvl, *Weqkvh, *Weqkvl, *Wiprjh, *Wiprjl, *Weprjh, *Weprjl;
    bf16 *Wim1h, *Wim1l, *Wtm1h, *Wtm1l, *Wim2h, *Wim2l, *Wtm2h, *Wtm2l;

    cudaGetSymbolAddress((void**)&E,     g_E);
    cudaGetSymbolAddress((void**)&QKVI,  g_QKVI);
    cudaGetSymbolAddress((void**)&QKVT,  g_QKVT);
    cudaGetSymbolAddress((void**)&Sb,    g_S);
    cudaGetSymbolAddress((void**)&NHh,   g_NHhi);  cudaGetSymbolAddress((void**)&NHl, g_NHlo);
    cudaGetSymbolAddress((void**)&NEh,   g_NEhi);  cudaGetSymbolAddress((void**)&NEl, g_NElo);
    cudaGetSymbolAddress((void**)&Qh,    g_Qhi);   cudaGetSymbolAddress((void**)&Ql,  g_Qlo);
    cudaGetSymbolAddress((void**)&Kh,    g_Khi);   cudaGetSymbolAddress((void**)&Kl,  g_Klo);
    cudaGetSymbolAddress((void**)&Vnh,   g_Vnh);   cudaGetSymbolAddress((void**)&Vnl, g_Vnl);
    cudaGetSymbolAddress((void**)&VTh,   g_VThi);  cudaGetSymbolAddress((void**)&VTl, g_VTlo);
    cudaGetSymbolAddress((void**)&Ph,    g_Phi);   cudaGetSymbolAddress((void**)&Pl,  g_Plo);
    cudaGetSymbolAddress((void**)&Oh,    g_Ohi);   cudaGetSymbolAddress((void**)&Ol,  g_Olo);
    cudaGetSymbolAddress((void**)&FFIh,  g_FFIhi); cudaGetSymbolAddress((void**)&FFIl, g_FFIlo);
    cudaGetSymbolAddress((void**)&FFTh,  g_FFThi); cudaGetSymbolAddress((void**)&FFTl, g_FFTlo);
    cudaGetSymbolAddress((void**)&Wiqkvh, g_Wiqkv_h); cudaGetSymbolAddress((void**)&Wiqkvl, g_Wiqkv_l);
    cudaGetSymbolAddress((void**)&Weqkvh, g_Weqkv_h); cudaGetSymbolAddress((void**)&Weqkvl, g_Weqkv_l);
    cudaGetSymbolAddress((void**)&Wiprjh, g_Wiprj_h); cudaGetSymbolAddress((void**)&Wiprjl, g_Wiprj_l);
    cudaGetSymbolAddress((void**)&Weprjh, g_Weprj_h); cudaGetSymbolAddress((void**)&Weprjl, g_Weprj_l);
    cudaGetSymbolAddress((void**)&Wim1h,  g_Wim1_h);  cudaGetSymbolAddress((void**)&Wim1l,  g_Wim1_l);
    cudaGetSymbolAddress((void**)&Wtm1h,  g_Wtm1_h);  cudaGetSymbolAddress((void**)&Wtm1l,  g_Wtm1_l);
    cudaGetSymbolAddress((void**)&Wim2h,  g_Wim2_h);  cudaGetSymbolAddress((void**)&Wim2l,  g_Wim2_l);
    cudaGetSymbolAddress((void**)&Wtm2h,  g_Wtm2_h);  cudaGetSymbolAddress((void**)&Wtm2l,  g_Wtm2_l);

    const float* Ei = E;
    const float* Et = E + 18432;

    cudaFuncSetAttribute(gemm_bf3<0>, cudaFuncAttributeMaxDynamicSharedMemorySize, SMEMSZ);
    cudaFuncSetAttribute(gemm_bf3<1>, cudaFuncAttributeMaxDynamicSharedMemorySize, SMEMSZ);
    cudaFuncSetAttribute(gemm_bf3<2>, cudaFuncAttributeMaxDynamicSharedMemorySize, SMEMSZ);
    cudaFuncSetAttribute(gemm_bf3<3>, cudaFuncAttributeMaxDynamicSharedMemorySize, SMEMSZ);

    dim3 tb(32, 8);
    transpose_kernel<<<dim3(9216 / 32, DIM / 32), tb>>>(W_iqkv,  Wiqkvh, Wiqkvl, DIM,  9216);
    transpose_kernel<<<dim3(9216 / 32, DIM / 32), tb>>>(W_eqkv,  Weqkvh, Weqkvl, DIM,  9216);
    transpose_kernel<<<dim3(DIM / 32, INNER / 32), tb>>>(W_iproj, Wiprjh, Wiprjl, INNER, DIM);
    transpose_kernel<<<dim3(DIM / 32, INNER / 32), tb>>>(W_eproj, Weprjh, Weprjl, INNER, DIM);
    transpose_kernel<<<dim3(MLPD / 32, DIM / 32), tb>>>(W_imlp1, Wim1h, Wim1l, DIM,  MLPD);
    transpose_kernel<<<dim3(MLPD / 32, DIM / 32), tb>>>(W_tmlp1, Wtm1h, Wtm1l, DIM,  MLPD);
    transpose_kernel<<<dim3(DIM / 32, MLPD / 32), tb>>>(W_imlp2, Wim2h, Wim2l, MLPD, DIM);
    transpose_kernel<<<dim3(DIM / 32, MLPD / 32), tb>>>(W_tmlp2, Wtm2h, Wtm2l, MLPD, DIM);

    // 1. adaLN embeddings
    ada_gemv_kernel<<<144, 256>>>(temb, W_iada, b_iada, W_tada, b_tada, E);

    // 2. LN + modulate (msa)
    adaln_kernel<<<LI + LT, 256>>>(hidden, enc, E, 0, 3072, NHh, NHl, NEh, NEl);

    // 3. QKV projections (img + txt fused) -> fp32
    {
        GemmSet si = { NHh, NHl, Wiqkvh, Wiqkvl, QKVI, nullptr, nullptr,
                       nullptr, nullptr, nullptr };
        GemmSet st = { NEh, NEl, Weqkvh, Weqkvl, QKVT, nullptr, nullptr,
                       nullptr, nullptr, nullptr };
        gemm_bf3<0><<<dim3(9216 / 128, (LI + LT) / 128), 128, SMEMSZ>>>(
            si, st, LI, 9216, DIM, 1.f);
    }

    // 4. RMS + RoPE + concat scatter (V natural), then coalesced V transpose
    rms_rope_kernel<<<Lseq * Hn, 128>>>(QKVT, QKVI, rot, q_scale, k_scale, eq_scale, ek_scale,
                                        Qh, Ql, Kh, Kl, Vnh, Vnl);
    transpose_bf_kernel<<<dim3(INNER / 32, Lseq / 32), tb>>>(Vnh, Vnl, VTh, VTl, Lseq, INNER);

    // 5. S = (Q K^T) / sqrt(DH) -> fp32
    {
        GemmSet ss = { Qh, Ql, Kh, Kl, Sb, nullptr, nullptr, nullptr, nullptr, nullptr };
        gemm_bf3<0><<<dim3(Lseq / 128, Lseq / 128), 128, SMEMSZ>>>(
            ss, ss, Lseq, Lseq, INNER, 0.08838834764831843f);
    }

    // 6. softmax -> P hi/lo
    softmax_kernel<<<Lseq, 256>>>(Sb, Ph, Pl);

    // 7. O = P V -> hi/lo
    {
        GemmSet so = { Ph, Pl, VTh, VTl, nullptr, Oh, Ol, nullptr, nullptr, nullptr };
        gemm_bf3<1><<<dim3(INNER / 128, Lseq / 128), 128, SMEMSZ>>>(
            so, so, Lseq, INNER, Lseq, 1.f);
    }

    // 8. output projections (img + txt fused) with gated residual -> d_out
    {
        GemmSet si = { Oh + (size_t)LT * INNER, Ol + (size_t)LT * INNER,
                       Wiprjh, Wiprjl, hs, nullptr, nullptr,
                       b_iproj, Ei + 6144, hidden };
        GemmSet st = { Oh, Ol, Weprjh, Weprjl, es, nullptr, nullptr,
                       b_eproj, Et + 6144, enc };
        gemm_bf3<2><<<dim3(DIM / 128, (LI + LT) / 128), 128, SMEMSZ>>>(
            si, st, LI, DIM, INNER, 1.f);
    }

    // 9. LN + modulate (mlp)
    adaln_kernel<<<LI + LT, 256>>>(hs, es, E, 9216, 12288, NHh, NHl, NEh, NEl);

    // 10. MLP1 + fused gelu (img + txt fused) -> hi/lo
    {
        GemmSet si = { NHh, NHl, Wim1h, Wim1l, nullptr, FFIh, FFIl,
                       b_imlp1, nullptr, nullptr };
        GemmSet st = { NEh, NEl, Wtm1h, Wtm1l, nullptr, FFTh, FFTl,
                       b_tmlp1, nullptr, nullptr };
        gemm_bf3<3><<<dim3(MLPD / 128, (LI + LT) / 128), 128, SMEMSZ>>>(
            si, st, LI, MLPD, DIM, 1.f);
    }

    // 11. MLP2 (img + txt fused) with gated residual (in-place on d_out)
    {
        GemmSet si = { FFIh, FFIl, Wim2h, Wim2l, hs, nullptr, nullptr,
                       b_imlp2, Ei + 15360, hs };
        GemmSet st = { FFTh, FFTl, Wtm2h, Wtm2l, es, nullptr, nullptr,
                       b_tmlp2, Et + 15360, es };
        gemm_bf3<2><<<dim3(DIM / 128, (LI + LT) / 128), 128, SMEMSZ>>>(
            si, st, LI, DIM, MLPD, 1.f);
    }
}